// round 3
// baseline (speedup 1.0000x reference)
#include <cuda_runtime.h>
#include <cstdint>

#define BB 2
#define SS 2048
#define DD 1024
#define HH 16
#define HD 64
#define MM (BB*SS)   // 4096

// ---- device scratch (no allocations allowed) ----
__device__ float g_Q[MM*DD];
__device__ float g_K[MM*DD];
__device__ float g_V[MM*DD];
__device__ float g_AO[MM*DD];
__device__ int   g_mask_mode;   // 0 = u8 bytes, 1 = 4-byte words

__device__ __forceinline__ uint32_t f2tf(float x) {
    uint32_t r;
    asm("cvt.rna.tf32.f32 %0, %1;" : "=r"(r) : "f"(x));
    return r;
}
__device__ __forceinline__ float u2f(uint32_t x) { return __uint_as_float(x); }
__device__ __forceinline__ float4 cvt4(float4 v) {
    float4 t;
    t.x = u2f(f2tf(v.x)); t.y = u2f(f2tf(v.y));
    t.z = u2f(f2tf(v.z)); t.w = u2f(f2tf(v.w));
    return t;
}

// D += A(16x8 row) * B(8x8 col) ; tf32 inputs, f32 accum
__device__ __forceinline__ void mma8(float* c, const uint32_t* a, const uint32_t* b) {
    asm volatile(
        "mma.sync.aligned.m16n8k8.row.col.f32.tf32.tf32.f32 "
        "{%0,%1,%2,%3}, {%4,%5,%6,%7}, {%8,%9}, {%0,%1,%2,%3};\n"
        : "+f"(c[0]), "+f"(c[1]), "+f"(c[2]), "+f"(c[3])
        : "r"(a[0]), "r"(a[1]), "r"(a[2]), "r"(a[3]), "r"(b[0]), "r"(b[1]));
}

// ---------------------------------------------------------------------------
__global__ void detect_mask_kernel(const unsigned int* __restrict__ m) {
    if (threadIdx.x == 0 && blockIdx.x == 0) {
        int wide = 1;
        for (int i = 0; i < 256; i++) {
            unsigned v = m[i];
            if (v != 0u && v != 1u && v != 0x3F800000u) { wide = 0; break; }
        }
        g_mask_mode = wide;
    }
}

// ---------------------------------------------------------------------------
// C[m,n] = sum_k A[m,k]*W[n,k] + bias[n], M=4096 (grid.x*128), N=K=1024.
// 128 threads (4 warps), block tile 128x128, warp tile 64x64, BK=16.
// Software pipelined: next K-slice LDG issued before the MMA block.
// ---------------------------------------------------------------------------
__device__ __forceinline__ void gemm_body(
    const float* __restrict__ A, const float* __restrict__ W,
    const float* __restrict__ bias, float* __restrict__ C)
{
    __shared__ __align__(16) float As[128][20];
    __shared__ __align__(16) float Bs[128][20];

    const int tid  = threadIdx.x;
    const int lane = tid & 31, wid = tid >> 5;
    const int g = lane >> 2, qq = lane & 3;
    const int wm = (wid & 1) * 64;
    const int wn = (wid >> 1) * 64;
    const int m0 = blockIdx.x * 128, n0 = blockIdx.y * 128;

    const float* Ap = A + (size_t)(m0 + tid) * DD;
    const float* Wp = W + (size_t)(n0 + tid) * DD;

    float4 sa[4], sb[4];
    #pragma unroll
    for (int c = 0; c < 4; c++) {
        sa[c] = *(const float4*)(Ap + c*4);
        sb[c] = *(const float4*)(Wp + c*4);
    }

    float acc[4][8][4];
    #pragma unroll
    for (int i = 0; i < 4; i++)
        #pragma unroll
        for (int j = 0; j < 8; j++)
            #pragma unroll
            for (int r = 0; r < 4; r++) acc[i][j][r] = 0.f;

    for (int k0 = 0; k0 < DD; k0 += 16) {
        __syncthreads();
        #pragma unroll
        for (int c = 0; c < 4; c++) {
            *(float4*)&As[tid][c*4] = cvt4(sa[c]);
            *(float4*)&Bs[tid][c*4] = cvt4(sb[c]);
        }
        __syncthreads();

        if (k0 + 16 < DD) {
            #pragma unroll
            for (int c = 0; c < 4; c++) {
                sa[c] = *(const float4*)(Ap + k0 + 16 + c*4);
                sb[c] = *(const float4*)(Wp + k0 + 16 + c*4);
            }
        }

        #pragma unroll
        for (int ks = 0; ks < 2; ks++) {
            const int kb = ks * 8;
            uint32_t aF[4][4], bF[8][2];
            #pragma unroll
            for (int j = 0; j < 8; j++) {
                bF[j][0] = __float_as_uint(Bs[wn + j*8 + g][kb + qq]);
                bF[j][1] = __float_as_uint(Bs[wn + j*8 + g][kb + qq + 4]);
            }
            #pragma unroll
            for (int i = 0; i < 4; i++) {
                aF[i][0] = __float_as_uint(As[wm + i*16 + g    ][kb + qq]);
                aF[i][1] = __float_as_uint(As[wm + i*16 + g + 8][kb + qq]);
                aF[i][2] = __float_as_uint(As[wm + i*16 + g    ][kb + qq + 4]);
                aF[i][3] = __float_as_uint(As[wm + i*16 + g + 8][kb + qq + 4]);
            }
            #pragma unroll
            for (int i = 0; i < 4; i++)
                #pragma unroll
                for (int j = 0; j < 8; j++)
                    mma8(acc[i][j], aF[i], bF[j]);
        }
    }

    #pragma unroll
    for (int j = 0; j < 8; j++) {
        const int col = n0 + wn + j*8 + 2*qq;
        const float2 bv = *(const float2*)&bias[col];
        #pragma unroll
        for (int i = 0; i < 4; i++) {
            const int row = m0 + wm + i*16 + g;
            *(float2*)&C[(size_t)row     * DD + col] =
                make_float2(acc[i][j][0] + bv.x, acc[i][j][1] + bv.y);
            *(float2*)&C[(size_t)(row+8) * DD + col] =
                make_float2(acc[i][j][2] + bv.x, acc[i][j][3] + bv.y);
        }
    }
}

__global__ __launch_bounds__(128) void gemm_one(
    const float* __restrict__ A, const float* __restrict__ W,
    const float* __restrict__ bias, float* __restrict__ C)
{
    gemm_body(A, W, bias, C);
}

__global__ __launch_bounds__(128) void gemm_qkv(
    const float* __restrict__ q, const float* __restrict__ k, const float* __restrict__ v,
    const float* __restrict__ Wq, const float* __restrict__ Wk, const float* __restrict__ Wv,
    const float* __restrict__ bq, const float* __restrict__ bk, const float* __restrict__ bv,
    float* __restrict__ Qo, float* __restrict__ Ko, float* __restrict__ Vo)
{
    const int z = blockIdx.z;
    const float* A = (z == 0) ? q : (z == 1) ? k : v;
    const float* W = (z == 0) ? Wq : (z == 1) ? Wk : Wv;
    const float* B = (z == 0) ? bq : (z == 1) ? bk : bv;
    float* C = (z == 0) ? Qo : (z == 1) ? Ko : Vo;
    gemm_body(A, W, B, C);
}

// ---------------------------------------------------------------------------
// Flash attention, tf32 mma. Block = (b, h, 128-query tile), 256 threads,
// 8 warps x 16 q rows. KV tiles 64x64, software-pipelined K/V prefetch,
// mask prefetch, and P kept in registers via the permuted-V trick:
// C-frag {c0,c2,c1,c3} is a valid A-frag if V rows use perm [0,2,4,6,1,3,5,7].
// ---------------------------------------------------------------------------
__global__ __launch_bounds__(256) void attn_tf32(
    const float* __restrict__ Qg, const float* __restrict__ Kg,
    const float* __restrict__ Vg, const void* __restrict__ maskp,
    float* __restrict__ Og)
{
    __shared__ __align__(16) float Ks[64][68];
    __shared__ __align__(16) float Vs[64][68];

    const int tid  = threadIdx.x;
    const int lane = tid & 31, wid = tid >> 5;
    const int g = lane >> 2, qq = lane & 3;
    const int q0 = blockIdx.x * 128, h = blockIdx.y, b = blockIdx.z;
    const int wide = g_mask_mode;

    const float* Qbase = Qg + ((size_t)(b*SS + q0))*DD + h*HD;
    const float* Kbase = Kg + ((size_t)b*SS)*DD + h*HD;
    const float* Vbase = Vg + ((size_t)b*SS)*DD + h*HD;
    const uint8_t* mask8  = (const uint8_t*)maskp + (size_t)b*SS*SS;
    const int*     mask32 = (const int*)maskp     + (size_t)b*SS*SS;

    const int r0 = wid*16 + g;
    const int r1 = r0 + 8;

    // Q fragments, pre-scaled by 1/sqrt(64)
    uint32_t aQ[8][4];
    #pragma unroll
    for (int kt = 0; kt < 8; kt++) {
        const int d0 = kt * 8;
        aQ[kt][0] = f2tf(0.125f * Qbase[(size_t)r0*DD + d0 + qq]);
        aQ[kt][1] = f2tf(0.125f * Qbase[(size_t)r1*DD + d0 + qq]);
        aQ[kt][2] = f2tf(0.125f * Qbase[(size_t)r0*DD + d0 + qq + 4]);
        aQ[kt][3] = f2tf(0.125f * Qbase[(size_t)r1*DD + d0 + qq + 4]);
    }

    // loader mapping: row = tid>>2 (0..63), cols (tid&3)*16 .. +15
    const int lrow = tid >> 2;
    const int lc0  = (tid & 3) * 16;
    const float* kp = Kbase + (size_t)lrow*DD + lc0;
    const float* vp = Vbase + (size_t)lrow*DD + lc0;

    float4 kst[4], vst[4];
    #pragma unroll
    for (int c = 0; c < 4; c++) {
        kst[c] = *(const float4*)(kp + c*4);
        vst[c] = *(const float4*)(vp + c*4);
    }

    float oacc[8][4];
    #pragma unroll
    for (int j = 0; j < 8; j++)
        #pragma unroll
        for (int r = 0; r < 4; r++) oacc[j][r] = 0.f;
    float m0r = -1e30f, m1r = -1e30f, l0 = 0.f, l1 = 0.f;

    for (int kv0 = 0; kv0 < SS; kv0 += 64) {
        __syncthreads();
        #pragma unroll
        for (int c = 0; c < 4; c++) {
            *(float4*)&Ks[lrow][lc0 + c*4] = cvt4(kst[c]);
            *(float4*)&Vs[lrow][lc0 + c*4] = cvt4(vst[c]);
        }
        __syncthreads();

        // prefetch next K/V tile
        if (kv0 + 64 < SS) {
            const size_t off = (size_t)(kv0 + 64) * DD;
            #pragma unroll
            for (int c = 0; c < 4; c++) {
                kst[c] = *(const float4*)(kp + off + c*4);
                vst[c] = *(const float4*)(vp + off + c*4);
            }
        }

        // prefetch current mask tile into registers
        int2 mA[8], mB[8];
        #pragma unroll
        for (int j = 0; j < 8; j++) {
            const int col = kv0 + j*8 + 2*qq;
            if (wide) {
                mA[j] = *(const int2*)(mask32 + (size_t)(q0+r0)*SS + col);
                mB[j] = *(const int2*)(mask32 + (size_t)(q0+r1)*SS + col);
            } else {
                unsigned a = *(const unsigned short*)(mask8 + (size_t)(q0+r0)*SS + col);
                unsigned bm = *(const unsigned short*)(mask8 + (size_t)(q0+r1)*SS + col);
                mA[j] = make_int2(a & 0xFFu, a >> 8);
                mB[j] = make_int2(bm & 0xFFu, bm >> 8);
            }
        }

        // S = Q K^T
        float sacc[8][4];
        #pragma unroll
        for (int j = 0; j < 8; j++)
            #pragma unroll
            for (int r = 0; r < 4; r++) sacc[j][r] = 0.f;

        #pragma unroll
        for (int kt = 0; kt < 8; kt++) {
            #pragma unroll
            for (int j = 0; j < 8; j++) {
                uint32_t bv[2];
                bv[0] = __float_as_uint(Ks[j*8 + g][kt*8 + qq]);
                bv[1] = __float_as_uint(Ks[j*8 + g][kt*8 + qq + 4]);
                mma8(sacc[j], aQ[kt], bv);
            }
        }

        // mask
        #pragma unroll
        for (int j = 0; j < 8; j++) {
            if (mA[j].x) sacc[j][0] = -1e30f;
            if (mA[j].y) sacc[j][1] = -1e30f;
            if (mB[j].x) sacc[j][2] = -1e30f;
            if (mB[j].y) sacc[j][3] = -1e30f;
        }

        // online softmax (quad reduce: rows live on 4 lanes g*4..g*4+3)
        float mx0 = -1e30f, mx1 = -1e30f;
        #pragma unroll
        for (int j = 0; j < 8; j++) {
            mx0 = fmaxf(mx0, fmaxf(sacc[j][0], sacc[j][1]));
            mx1 = fmaxf(mx1, fmaxf(sacc[j][2], sacc[j][3]));
        }
        mx0 = fmaxf(mx0, __shfl_xor_sync(0xffffffffu, mx0, 1));
        mx0 = fmaxf(mx0, __shfl_xor_sync(0xffffffffu, mx0, 2));
        mx1 = fmaxf(mx1, __shfl_xor_sync(0xffffffffu, mx1, 1));
        mx1 = fmaxf(mx1, __shfl_xor_sync(0xffffffffu, mx1, 2));

        const float mn0 = fmaxf(m0r, mx0), mn1 = fmaxf(m1r, mx1);
        const float al0 = __expf(m0r - mn0), al1 = __expf(m1r - mn1);
        m0r = mn0; m1r = mn1;

        float s0 = 0.f, s1 = 0.f;
        #pragma unroll
        for (int j = 0; j < 8; j++) {
            float p0 = __expf(sacc[j][0] - mn0);
            float p1 = __expf(sacc[j][1] - mn0);
            float p2 = __expf(sacc[j][2] - mn1);
            float p3 = __expf(sacc[j][3] - mn1);
            sacc[j][0] = p0; sacc[j][1] = p1; sacc[j][2] = p2; sacc[j][3] = p3;
            s0 += p0 + p1; s1 += p2 + p3;
        }
        s0 += __shfl_xor_sync(0xffffffffu, s0, 1);
        s0 += __shfl_xor_sync(0xffffffffu, s0, 2);
        s1 += __shfl_xor_sync(0xffffffffu, s1, 1);
        s1 += __shfl_xor_sync(0xffffffffu, s1, 2);
        l0 = l0*al0 + s0;
        l1 = l1*al1 + s1;
        #pragma unroll
        for (int j = 0; j < 8; j++) {
            oacc[j][0] *= al0; oacc[j][1] *= al0;
            oacc[j][2] *= al1; oacc[j][3] *= al1;
        }

        // O += P @ V : P stays in registers; C-frag -> A-frag by relabel
        // {a0,a1,a2,a3} = {c0,c2,c1,c3}; V rows permuted qq -> 2qq, qq+4 -> 2qq+1
        #pragma unroll
        for (int kt = 0; kt < 8; kt++) {
            uint32_t aP[4];
            aP[0] = f2tf(sacc[kt][0]);
            aP[1] = f2tf(sacc[kt][2]);
            aP[2] = f2tf(sacc[kt][1]);
            aP[3] = f2tf(sacc[kt][3]);
            #pragma unroll
            for (int j = 0; j < 8; j++) {
                uint32_t bv[2];
                bv[0] = __float_as_uint(Vs[kt*8 + 2*qq    ][j*8 + g]);
                bv[1] = __float_as_uint(Vs[kt*8 + 2*qq + 1][j*8 + g]);
                mma8(oacc[j], aP, bv);
            }
        }
    }

    // epilogue
    const float inv0 = 1.0f / l0, inv1 = 1.0f / l1;
    #pragma unroll
    for (int j = 0; j < 8; j++) {
        *(float2*)&Og[((size_t)(b*SS + q0 + r0))*DD + h*HD + j*8 + 2*qq] =
            make_float2(oacc[j][0]*inv0, oacc[j][1]*inv0);
        *(float2*)&Og[((size_t)(b*SS + q0 + r1))*DD + h*HD + j*8 + 2*qq] =
            make_float2(oacc[j][2]*inv1, oacc[j][3]*inv1);
    }
}

// ---------------------------------------------------------------------------
extern "C" void kernel_launch(void* const* d_in, const int* in_sizes, int n_in,
                              void* d_out, int out_size)
{
    const float* query = (const float*)d_in[0];
    const float* key   = (const float*)d_in[1];
    const float* value = (const float*)d_in[2];
    const void*  mask  = d_in[3];
    const float* Wq = (const float*)d_in[4];
    const float* Wk = (const float*)d_in[5];
    const float* Wv = (const float*)d_in[6];
    const float* Wo = (const float*)d_in[7];
    const float* bq = (const float*)d_in[8];
    const float* bk = (const float*)d_in[9];
    const float* bv = (const float*)d_in[10];
    const float* bo = (const float*)d_in[11];
    float* out = (float*)d_out;

    float *Qp, *Kp, *Vp, *AOp;
    cudaGetSymbolAddress((void**)&Qp,  g_Q);
    cudaGetSymbolAddress((void**)&Kp,  g_K);
    cudaGetSymbolAddress((void**)&Vp,  g_V);
    cudaGetSymbolAddress((void**)&AOp, g_AO);

    detect_mask_kernel<<<1, 32>>>((const unsigned int*)mask);

    dim3 qkv_grid(MM/128, DD/128, 3);   // (32, 8, 3)
    gemm_qkv<<<qkv_grid, 128>>>(query, key, value, Wq, Wk, Wv,
                                bq, bk, bv, Qp, Kp, Vp);

    dim3 agrid(SS/128, HH, BB);         // (16, 16, 2)
    attn_tf32<<<agrid, 256>>>(Qp, Kp, Vp, mask, AOp);

    dim3 ggrid(MM/128, DD/128);         // (32, 8)
    gemm_one<<<ggrid, 128>>>(AOp, Wo, bo, out);
}

// round 4
// speedup vs baseline: 1.0559x; 1.0559x over previous
#include <cuda_runtime.h>
#include <cstdint>

#define BB 2
#define SS 2048
#define DD 1024
#define HH 16
#define HD 64
#define MM (BB*SS)   // 4096

// ---- device scratch (no allocations allowed) ----
__device__ float g_Q[MM*DD];
__device__ float g_K[MM*DD];
__device__ float g_V[MM*DD];
__device__ float g_AO[MM*DD];
__device__ int   g_mask_mode;   // 0 = u8 bytes, 1 = 4-byte words

__device__ __forceinline__ uint32_t f2tf(float x) {
    uint32_t r;
    asm("cvt.rna.tf32.f32 %0, %1;" : "=r"(r) : "f"(x));
    return r;
}
__device__ __forceinline__ float u2f(uint32_t x) { return __uint_as_float(x); }
__device__ __forceinline__ float4 cvt4(float4 v) {
    float4 t;
    t.x = u2f(f2tf(v.x)); t.y = u2f(f2tf(v.y));
    t.z = u2f(f2tf(v.z)); t.w = u2f(f2tf(v.w));
    return t;
}

// D += A(16x8 row) * B(8x8 col) ; tf32 inputs, f32 accum
__device__ __forceinline__ void mma8(float* c, const uint32_t* a, const uint32_t* b) {
    asm volatile(
        "mma.sync.aligned.m16n8k8.row.col.f32.tf32.tf32.f32 "
        "{%0,%1,%2,%3}, {%4,%5,%6,%7}, {%8,%9}, {%0,%1,%2,%3};\n"
        : "+f"(c[0]), "+f"(c[1]), "+f"(c[2]), "+f"(c[3])
        : "r"(a[0]), "r"(a[1]), "r"(a[2]), "r"(a[3]), "r"(b[0]), "r"(b[1]));
}

// ---------------------------------------------------------------------------
__global__ void detect_mask_kernel(const unsigned int* __restrict__ m) {
    if (threadIdx.x == 0 && blockIdx.x == 0) {
        int wide = 1;
        for (int i = 0; i < 256; i++) {
            unsigned v = m[i];
            if (v != 0u && v != 1u && v != 0x3F800000u) { wide = 0; break; }
        }
        g_mask_mode = wide;
    }
}

// ---------------------------------------------------------------------------
// C[m,n] = sum_k A[m,k]*W[n,k] + bias[n], N=K=1024.
// 256 threads (8 warps 2x4), block 128x128, warp tile 64x32, BK=16.
// Double-buffered smem (1 sync/iter) + register prefetch of next K-slice.
// ---------------------------------------------------------------------------
__device__ __forceinline__ void gemm_body(
    const float* __restrict__ A, const float* __restrict__ W,
    const float* __restrict__ bias, float* __restrict__ C)
{
    __shared__ __align__(16) float As[2][128][20];
    __shared__ __align__(16) float Bs[2][128][20];

    const int tid  = threadIdx.x;
    const int lane = tid & 31, wid = tid >> 5;
    const int g = lane >> 2, qq = lane & 3;
    const int wm = (wid & 1) * 64;
    const int wn = (wid >> 1) * 32;
    const int m0 = blockIdx.x * 128, n0 = blockIdx.y * 128;

    const int lr = tid >> 1;            // 0..127
    const int lc = (tid & 1) * 8;       // 0 or 8

    const float* Ap = A + (size_t)(m0 + lr) * DD + lc;
    const float* Wp = W + (size_t)(n0 + lr) * DD + lc;

    float4 ra0, ra1, rb0, rb1;
    ra0 = *(const float4*)(Ap);     ra1 = *(const float4*)(Ap + 4);
    rb0 = *(const float4*)(Wp);     rb1 = *(const float4*)(Wp + 4);
    *(float4*)&As[0][lr][lc]   = cvt4(ra0);
    *(float4*)&As[0][lr][lc+4] = cvt4(ra1);
    *(float4*)&Bs[0][lr][lc]   = cvt4(rb0);
    *(float4*)&Bs[0][lr][lc+4] = cvt4(rb1);
    __syncthreads();

    float acc[4][4][4];
    #pragma unroll
    for (int i = 0; i < 4; i++)
        #pragma unroll
        for (int j = 0; j < 4; j++)
            #pragma unroll
            for (int r = 0; r < 4; r++) acc[i][j][r] = 0.f;

    int p = 0;
    for (int k0 = 0; k0 < DD; k0 += 16) {
        const bool more = (k0 + 16) < DD;
        if (more) {
            ra0 = *(const float4*)(Ap + k0 + 16);
            ra1 = *(const float4*)(Ap + k0 + 20);
            rb0 = *(const float4*)(Wp + k0 + 16);
            rb1 = *(const float4*)(Wp + k0 + 20);
        }

        #pragma unroll
        for (int ks = 0; ks < 2; ks++) {
            const int kb = ks * 8;
            uint32_t aF[4][4], bF[4][2];
            #pragma unroll
            for (int j = 0; j < 4; j++) {
                bF[j][0] = __float_as_uint(Bs[p][wn + j*8 + g][kb + qq]);
                bF[j][1] = __float_as_uint(Bs[p][wn + j*8 + g][kb + qq + 4]);
            }
            #pragma unroll
            for (int i = 0; i < 4; i++) {
                aF[i][0] = __float_as_uint(As[p][wm + i*16 + g    ][kb + qq]);
                aF[i][1] = __float_as_uint(As[p][wm + i*16 + g + 8][kb + qq]);
                aF[i][2] = __float_as_uint(As[p][wm + i*16 + g    ][kb + qq + 4]);
                aF[i][3] = __float_as_uint(As[p][wm + i*16 + g + 8][kb + qq + 4]);
            }
            #pragma unroll
            for (int i = 0; i < 4; i++)
                #pragma unroll
                for (int j = 0; j < 4; j++)
                    mma8(acc[i][j], aF[i], bF[j]);
        }

        if (more) {
            *(float4*)&As[p^1][lr][lc]   = cvt4(ra0);
            *(float4*)&As[p^1][lr][lc+4] = cvt4(ra1);
            *(float4*)&Bs[p^1][lr][lc]   = cvt4(rb0);
            *(float4*)&Bs[p^1][lr][lc+4] = cvt4(rb1);
        }
        __syncthreads();
        p ^= 1;
    }

    #pragma unroll
    for (int j = 0; j < 4; j++) {
        const int col = n0 + wn + j*8 + 2*qq;
        const float2 bv = *(const float2*)&bias[col];
        #pragma unroll
        for (int i = 0; i < 4; i++) {
            const int row = m0 + wm + i*16 + g;
            *(float2*)&C[(size_t)row     * DD + col] =
                make_float2(acc[i][j][0] + bv.x, acc[i][j][1] + bv.y);
            *(float2*)&C[(size_t)(row+8) * DD + col] =
                make_float2(acc[i][j][2] + bv.x, acc[i][j][3] + bv.y);
        }
    }
}

__global__ __launch_bounds__(256) void gemm_one(
    const float* __restrict__ A, const float* __restrict__ W,
    const float* __restrict__ bias, float* __restrict__ C)
{
    gemm_body(A, W, bias, C);
}

__global__ __launch_bounds__(256) void gemm_qkv(
    const float* __restrict__ q, const float* __restrict__ k, const float* __restrict__ v,
    const float* __restrict__ Wq, const float* __restrict__ Wk, const float* __restrict__ Wv,
    const float* __restrict__ bq, const float* __restrict__ bk, const float* __restrict__ bv,
    float* __restrict__ Qo, float* __restrict__ Ko, float* __restrict__ Vo)
{
    const int z = blockIdx.z;
    const float* A = (z == 0) ? q : (z == 1) ? k : v;
    const float* W = (z == 0) ? Wq : (z == 1) ? Wk : Wv;
    const float* B = (z == 0) ? bq : (z == 1) ? bk : bv;
    float* C = (z == 0) ? Qo : (z == 1) ? Ko : Vo;
    gemm_body(A, W, B, C);
}

// ---------------------------------------------------------------------------
// Flash attention, tf32 mma (unchanged from R3). Block = (b, h, 128-q tile),
// 256 threads, 8 warps x 16 q rows. KV tiles 64x64, K/V + mask prefetch,
// P kept in registers via permuted-V trick.
// ---------------------------------------------------------------------------
__global__ __launch_bounds__(256) void attn_tf32(
    const float* __restrict__ Qg, const float* __restrict__ Kg,
    const float* __restrict__ Vg, const void* __restrict__ maskp,
    float* __restrict__ Og)
{
    __shared__ __align__(16) float Ks[64][68];
    __shared__ __align__(16) float Vs[64][68];

    const int tid  = threadIdx.x;
    const int lane = tid & 31, wid = tid >> 5;
    const int g = lane >> 2, qq = lane & 3;
    const int q0 = blockIdx.x * 128, h = blockIdx.y, b = blockIdx.z;
    const int wide = g_mask_mode;

    const float* Qbase = Qg + ((size_t)(b*SS + q0))*DD + h*HD;
    const float* Kbase = Kg + ((size_t)b*SS)*DD + h*HD;
    const float* Vbase = Vg + ((size_t)b*SS)*DD + h*HD;
    const uint8_t* mask8  = (const uint8_t*)maskp + (size_t)b*SS*SS;
    const int*     mask32 = (const int*)maskp     + (size_t)b*SS*SS;

    const int r0 = wid*16 + g;
    const int r1 = r0 + 8;

    uint32_t aQ[8][4];
    #pragma unroll
    for (int kt = 0; kt < 8; kt++) {
        const int d0 = kt * 8;
        aQ[kt][0] = f2tf(0.125f * Qbase[(size_t)r0*DD + d0 + qq]);
        aQ[kt][1] = f2tf(0.125f * Qbase[(size_t)r1*DD + d0 + qq]);
        aQ[kt][2] = f2tf(0.125f * Qbase[(size_t)r0*DD + d0 + qq + 4]);
        aQ[kt][3] = f2tf(0.125f * Qbase[(size_t)r1*DD + d0 + qq + 4]);
    }

    const int lrow = tid >> 2;
    const int lc0  = (tid & 3) * 16;
    const float* kp = Kbase + (size_t)lrow*DD + lc0;
    const float* vp = Vbase + (size_t)lrow*DD + lc0;

    float4 kst[4], vst[4];
    #pragma unroll
    for (int c = 0; c < 4; c++) {
        kst[c] = *(const float4*)(kp + c*4);
        vst[c] = *(const float4*)(vp + c*4);
    }

    float oacc[8][4];
    #pragma unroll
    for (int j = 0; j < 8; j++)
        #pragma unroll
        for (int r = 0; r < 4; r++) oacc[j][r] = 0.f;
    float m0r = -1e30f, m1r = -1e30f, l0 = 0.f, l1 = 0.f;

    for (int kv0 = 0; kv0 < SS; kv0 += 64) {
        __syncthreads();
        #pragma unroll
        for (int c = 0; c < 4; c++) {
            *(float4*)&Ks[lrow][lc0 + c*4] = cvt4(kst[c]);
            *(float4*)&Vs[lrow][lc0 + c*4] = cvt4(vst[c]);
        }
        __syncthreads();

        if (kv0 + 64 < SS) {
            const size_t off = (size_t)(kv0 + 64) * DD;
            #pragma unroll
            for (int c = 0; c < 4; c++) {
                kst[c] = *(const float4*)(kp + off + c*4);
                vst[c] = *(const float4*)(vp + off + c*4);
            }
        }

        int2 mA[8], mB[8];
        #pragma unroll
        for (int j = 0; j < 8; j++) {
            const int col = kv0 + j*8 + 2*qq;
            if (wide) {
                mA[j] = *(const int2*)(mask32 + (size_t)(q0+r0)*SS + col);
                mB[j] = *(const int2*)(mask32 + (size_t)(q0+r1)*SS + col);
            } else {
                unsigned a  = *(const unsigned short*)(mask8 + (size_t)(q0+r0)*SS + col);
                unsigned bm = *(const unsigned short*)(mask8 + (size_t)(q0+r1)*SS + col);
                mA[j] = make_int2(a & 0xFFu, a >> 8);
                mB[j] = make_int2(bm & 0xFFu, bm >> 8);
            }
        }

        float sacc[8][4];
        #pragma unroll
        for (int j = 0; j < 8; j++)
            #pragma unroll
            for (int r = 0; r < 4; r++) sacc[j][r] = 0.f;

        #pragma unroll
        for (int kt = 0; kt < 8; kt++) {
            #pragma unroll
            for (int j = 0; j < 8; j++) {
                uint32_t bv[2];
                bv[0] = __float_as_uint(Ks[j*8 + g][kt*8 + qq]);
                bv[1] = __float_as_uint(Ks[j*8 + g][kt*8 + qq + 4]);
                mma8(sacc[j], aQ[kt], bv);
            }
        }

        #pragma unroll
        for (int j = 0; j < 8; j++) {
            if (mA[j].x) sacc[j][0] = -1e30f;
            if (mA[j].y) sacc[j][1] = -1e30f;
            if (mB[j].x) sacc[j][2] = -1e30f;
            if (mB[j].y) sacc[j][3] = -1e30f;
        }

        float mx0 = -1e30f, mx1 = -1e30f;
        #pragma unroll
        for (int j = 0; j < 8; j++) {
            mx0 = fmaxf(mx0, fmaxf(sacc[j][0], sacc[j][1]));
            mx1 = fmaxf(mx1, fmaxf(sacc[j][2], sacc[j][3]));
        }
        mx0 = fmaxf(mx0, __shfl_xor_sync(0xffffffffu, mx0, 1));
        mx0 = fmaxf(mx0, __shfl_xor_sync(0xffffffffu, mx0, 2));
        mx1 = fmaxf(mx1, __shfl_xor_sync(0xffffffffu, mx1, 1));
        mx1 = fmaxf(mx1, __shfl_xor_sync(0xffffffffu, mx1, 2));

        const float mn0 = fmaxf(m0r, mx0), mn1 = fmaxf(m1r, mx1);
        const float al0 = __expf(m0r - mn0), al1 = __expf(m1r - mn1);
        m0r = mn0; m1r = mn1;

        float s0 = 0.f, s1 = 0.f;
        #pragma unroll
        for (int j = 0; j < 8; j++) {
            float p0 = __expf(sacc[j][0] - mn0);
            float p1 = __expf(sacc[j][1] - mn0);
            float p2 = __expf(sacc[j][2] - mn1);
            float p3 = __expf(sacc[j][3] - mn1);
            sacc[j][0] = p0; sacc[j][1] = p1; sacc[j][2] = p2; sacc[j][3] = p3;
            s0 += p0 + p1; s1 += p2 + p3;
        }
        s0 += __shfl_xor_sync(0xffffffffu, s0, 1);
        s0 += __shfl_xor_sync(0xffffffffu, s0, 2);
        s1 += __shfl_xor_sync(0xffffffffu, s1, 1);
        s1 += __shfl_xor_sync(0xffffffffu, s1, 2);
        l0 = l0*al0 + s0;
        l1 = l1*al1 + s1;
        #pragma unroll
        for (int j = 0; j < 8; j++) {
            oacc[j][0] *= al0; oacc[j][1] *= al0;
            oacc[j][2] *= al1; oacc[j][3] *= al1;
        }

        #pragma unroll
        for (int kt = 0; kt < 8; kt++) {
            uint32_t aP[4];
            aP[0] = f2tf(sacc[kt][0]);
            aP[1] = f2tf(sacc[kt][2]);
            aP[2] = f2tf(sacc[kt][1]);
            aP[3] = f2tf(sacc[kt][3]);
            #pragma unroll
            for (int j = 0; j < 8; j++) {
                uint32_t bv[2];
                bv[0] = __float_as_uint(Vs[kt*8 + 2*qq    ][j*8 + g]);
                bv[1] = __float_as_uint(Vs[kt*8 + 2*qq + 1][j*8 + g]);
                mma8(oacc[j], aP, bv);
            }
        }
    }

    const float inv0 = 1.0f / l0, inv1 = 1.0f / l1;
    #pragma unroll
    for (int j = 0; j < 8; j++) {
        *(float2*)&Og[((size_t)(b*SS + q0 + r0))*DD + h*HD + j*8 + 2*qq] =
            make_float2(oacc[j][0]*inv0, oacc[j][1]*inv0);
        *(float2*)&Og[((size_t)(b*SS + q0 + r1))*DD + h*HD + j*8 + 2*qq] =
            make_float2(oacc[j][2]*inv1, oacc[j][3]*inv1);
    }
}

// ---------------------------------------------------------------------------
extern "C" void kernel_launch(void* const* d_in, const int* in_sizes, int n_in,
                              void* d_out, int out_size)
{
    const float* query = (const float*)d_in[0];
    const float* key   = (const float*)d_in[1];
    const float* value = (const float*)d_in[2];
    const void*  mask  = d_in[3];
    const float* Wq = (const float*)d_in[4];
    const float* Wk = (const float*)d_in[5];
    const float* Wv = (const float*)d_in[6];
    const float* Wo = (const float*)d_in[7];
    const float* bq = (const float*)d_in[8];
    const float* bk = (const float*)d_in[9];
    const float* bv = (const float*)d_in[10];
    const float* bo = (const float*)d_in[11];
    float* out = (float*)d_out;

    float *Qp, *Kp, *Vp, *AOp;
    cudaGetSymbolAddress((void**)&Qp,  g_Q);
    cudaGetSymbolAddress((void**)&Kp,  g_K);
    cudaGetSymbolAddress((void**)&Vp,  g_V);
    cudaGetSymbolAddress((void**)&AOp, g_AO);

    detect_mask_kernel<<<1, 32>>>((const unsigned int*)mask);

    dim3 qkv_grid(MM/128, DD/128, 3);   // (32, 8, 3)
    gemm_qkv<<<qkv_grid, 256>>>(query, key, value, Wq, Wk, Wv,
                                bq, bk, bv, Qp, Kp, Vp);

    dim3 agrid(SS/128, HH, BB);         // (16, 16, 2)
    attn_tf32<<<agrid, 256>>>(Qp, Kp, Vp, mask, AOp);

    dim3 ggrid(MM/128, DD/128);         // (32, 8)
    gemm_one<<<ggrid, 256>>>(AOp, Wo, bo, out);
}

// round 5
// speedup vs baseline: 1.2281x; 1.1630x over previous
#include <cuda_runtime.h>
#include <cstdint>

#define BB 2
#define SS 2048
#define DD 1024
#define HH 16
#define HD 64
#define MM (BB*SS)   // 4096

// ---- device scratch (no allocations allowed) ----
__device__ float g_Q[MM*DD];
__device__ float g_K[MM*DD];
__device__ float g_V[MM*DD];
__device__ float g_AO[MM*DD];
__device__ float g_rq[MM*DD];
__device__ float g_rk[MM*DD];
__device__ float g_rv[MM*DD];
__device__ float g_rW[4][DD*DD];
__device__ int   g_mask_mode;   // 0 = u8 bytes, 1 = 4-byte words

__device__ __forceinline__ uint32_t f2tf(float x) {
    uint32_t r;
    asm("cvt.rna.tf32.f32 %0, %1;" : "=r"(r) : "f"(x));
    return r;
}
__device__ __forceinline__ float u2f(uint32_t x) { return __uint_as_float(x); }
__device__ __forceinline__ float4 cvt4(float4 v) {
    float4 t;
    t.x = u2f(f2tf(v.x)); t.y = u2f(f2tf(v.y));
    t.z = u2f(f2tf(v.z)); t.w = u2f(f2tf(v.w));
    return t;
}

__device__ __forceinline__ void cp16(uint32_t dst, const void* src) {
    asm volatile("cp.async.cg.shared.global [%0], [%1], 16;" :: "r"(dst), "l"(src));
}
#define CP_COMMIT() asm volatile("cp.async.commit_group;")
#define CP_WAIT(n)  asm volatile("cp.async.wait_group %0;" :: "n"(n))

// D += A(16x8 row) * B(8x8 col) ; tf32 inputs, f32 accum
__device__ __forceinline__ void mma8(float* c, const uint32_t* a, const uint32_t* b) {
    asm volatile(
        "mma.sync.aligned.m16n8k8.row.col.f32.tf32.tf32.f32 "
        "{%0,%1,%2,%3}, {%4,%5,%6,%7}, {%8,%9}, {%0,%1,%2,%3};\n"
        : "+f"(c[0]), "+f"(c[1]), "+f"(c[2]), "+f"(c[3])
        : "r"(a[0]), "r"(a[1]), "r"(a[2]), "r"(a[3]), "r"(b[0]), "r"(b[1]));
}

// ---------------------------------------------------------------------------
__global__ void detect_mask_kernel(const unsigned int* __restrict__ m) {
    if (threadIdx.x == 0 && blockIdx.x == 0) {
        int wide = 1;
        for (int i = 0; i < 256; i++) {
            unsigned v = m[i];
            if (v != 0u && v != 1u && v != 0x3F800000u) { wide = 0; break; }
        }
        g_mask_mode = wide;
    }
}

// ---------------------------------------------------------------------------
// Pre-round inputs + weights to tf32 (so GEMM mainloop can cp.async raw bytes).
// grid.y: 0..2 inputs (MM*DD), 3..6 weights (DD*DD)
// ---------------------------------------------------------------------------
__global__ __launch_bounds__(256) void round_all(
    const float* __restrict__ q, const float* __restrict__ k, const float* __restrict__ v,
    const float* __restrict__ wq, const float* __restrict__ wk,
    const float* __restrict__ wv, const float* __restrict__ wo,
    float* __restrict__ rq, float* __restrict__ rk, float* __restrict__ rv,
    float* __restrict__ rW)
{
    const int y = blockIdx.y;
    const float4* src; float4* dst; int n4;
    if (y < 3) {
        src = (const float4*)(y == 0 ? q : y == 1 ? k : v);
        dst = (float4*)(y == 0 ? rq : y == 1 ? rk : rv);
        n4 = MM*DD/4;
    } else {
        src = (const float4*)(y == 3 ? wq : y == 4 ? wk : y == 5 ? wv : wo);
        dst = (float4*)(rW + (size_t)(y-3)*DD*DD);
        n4 = DD*DD/4;
    }
    int i = blockIdx.x*blockDim.x + threadIdx.x;
    const int stride = gridDim.x*blockDim.x;
    for (; i < n4; i += stride) dst[i] = cvt4(src[i]);
}

// ---------------------------------------------------------------------------
// C[m,n] = sum_k A[m,k]*W[n,k] + bias[n], N=K=1024, inputs pre-rounded tf32.
// 256 threads (8 warps 2x4), block 128x128, warp 64x32, BK=16,
// 4-stage cp.async pipeline. Dynamic smem: As[4][128][20] + Bs[4][128][20].
// ---------------------------------------------------------------------------
#define GSTG 4
#define GS_F (128*20)           // floats per stage per matrix
#define GS_B (GS_F*4)           // bytes per stage per matrix
#define GEMM_SMEM (GSTG*GS_B*2) // 81920

template<bool ROUND>
__device__ __forceinline__ void gemm_body(
    const float* __restrict__ A, const float* __restrict__ W,
    const float* __restrict__ bias, float* __restrict__ C)
{
    extern __shared__ float dsm[];
    float* Asm = dsm;                 // [GSTG][128][20]
    float* Bsm = dsm + GSTG*GS_F;     // [GSTG][128][20]

    const int tid  = threadIdx.x;
    const int lane = tid & 31, wid = tid >> 5;
    const int g = lane >> 2, qq = lane & 3;
    const int wm = (wid & 1) * 64;
    const int wn = (wid >> 1) * 32;
    const int m0 = blockIdx.x * 128, n0 = blockIdx.y * 128;

    const int lr = tid >> 1;            // 0..127
    const int lc = (tid & 1) * 8;       // 0 or 8

    const float* Ap = A + (size_t)(m0 + lr) * DD + lc;
    const float* Wp = W + (size_t)(n0 + lr) * DD + lc;
    const uint32_t a_s = (uint32_t)__cvta_generic_to_shared(Asm + lr*20 + lc);
    const uint32_t b_s = (uint32_t)__cvta_generic_to_shared(Bsm + lr*20 + lc);

    auto fill = [&](int s, int k0) {
        const uint32_t aa = a_s + s*GS_B, ba = b_s + s*GS_B;
        cp16(aa,      Ap + k0);
        cp16(aa + 16, Ap + k0 + 4);
        cp16(ba,      Wp + k0);
        cp16(ba + 16, Wp + k0 + 4);
    };

    #pragma unroll
    for (int s = 0; s < GSTG-1; s++) { fill(s, s*16); CP_COMMIT(); }

    float acc[4][4][4];
    #pragma unroll
    for (int i = 0; i < 4; i++)
        #pragma unroll
        for (int j = 0; j < 4; j++)
            #pragma unroll
            for (int r = 0; r < 4; r++) acc[i][j][r] = 0.f;

    const int NIT = DD/16;  // 64
    for (int it = 0; it < NIT; it++) {
        CP_WAIT(GSTG-2);
        __syncthreads();
        if (it + GSTG-1 < NIT) fill((it + GSTG-1) & (GSTG-1), (it + GSTG-1)*16);
        CP_COMMIT();

        const float* As = Asm + (it & (GSTG-1))*GS_F;
        const float* Bs = Bsm + (it & (GSTG-1))*GS_F;

        #pragma unroll
        for (int ks = 0; ks < 2; ks++) {
            const int kb = ks * 8;
            uint32_t aF[4][4], bF[4][2];
            #pragma unroll
            for (int j = 0; j < 4; j++) {
                bF[j][0] = __float_as_uint(Bs[(wn + j*8 + g)*20 + kb + qq]);
                bF[j][1] = __float_as_uint(Bs[(wn + j*8 + g)*20 + kb + qq + 4]);
            }
            #pragma unroll
            for (int i = 0; i < 4; i++) {
                aF[i][0] = __float_as_uint(As[(wm + i*16 + g    )*20 + kb + qq]);
                aF[i][1] = __float_as_uint(As[(wm + i*16 + g + 8)*20 + kb + qq]);
                aF[i][2] = __float_as_uint(As[(wm + i*16 + g    )*20 + kb + qq + 4]);
                aF[i][3] = __float_as_uint(As[(wm + i*16 + g + 8)*20 + kb + qq + 4]);
            }
            #pragma unroll
            for (int i = 0; i < 4; i++)
                #pragma unroll
                for (int j = 0; j < 4; j++)
                    mma8(acc[i][j], aF[i], bF[j]);
        }
    }

    #pragma unroll
    for (int j = 0; j < 4; j++) {
        const int col = n0 + wn + j*8 + 2*qq;
        const float2 bv = *(const float2*)&bias[col];
        #pragma unroll
        for (int i = 0; i < 4; i++) {
            const int row = m0 + wm + i*16 + g;
            float2 o0 = make_float2(acc[i][j][0] + bv.x, acc[i][j][1] + bv.y);
            float2 o1 = make_float2(acc[i][j][2] + bv.x, acc[i][j][3] + bv.y);
            if (ROUND) {
                o0.x = u2f(f2tf(o0.x)); o0.y = u2f(f2tf(o0.y));
                o1.x = u2f(f2tf(o1.x)); o1.y = u2f(f2tf(o1.y));
            }
            *(float2*)&C[(size_t)row     * DD + col] = o0;
            *(float2*)&C[(size_t)(row+8) * DD + col] = o1;
        }
    }
}

__global__ __launch_bounds__(256, 2) void gemm_out(
    const float* __restrict__ A, const float* __restrict__ W,
    const float* __restrict__ bias, float* __restrict__ C)
{
    gemm_body<false>(A, W, bias, C);
}

__global__ __launch_bounds__(256, 2) void gemm_qkv(
    const float* __restrict__ rq, const float* __restrict__ rk, const float* __restrict__ rv,
    const float* __restrict__ rW,
    const float* __restrict__ bq, const float* __restrict__ bk, const float* __restrict__ bv,
    float* __restrict__ Qo, float* __restrict__ Ko, float* __restrict__ Vo)
{
    const int z = blockIdx.z;
    const float* A = (z == 0) ? rq : (z == 1) ? rk : rv;
    const float* W = rW + (size_t)z*DD*DD;
    const float* B = (z == 0) ? bq : (z == 1) ? bk : bv;
    float* C = (z == 0) ? Qo : (z == 1) ? Ko : Vo;
    gemm_body<true>(A, W, B, C);
}

// ---------------------------------------------------------------------------
// Flash attention, tf32 mma. Block = (b, h, 128-q tile), 256 threads, 8 warps.
// KV tiles 64x64 via 2-stage cp.async (inputs already tf32-rounded).
// P in registers (permuted-V trick). Mask packed into 2 bit-registers.
// Dynamic smem: K[2][64][68] + V[2][64][68] = 69632 B.
// ---------------------------------------------------------------------------
#define AS_F (64*68)
#define AS_B (AS_F*4)
#define ATTN_SMEM (4*AS_B)

__global__ __launch_bounds__(256, 2) void attn_tf32(
    const float* __restrict__ Qg, const float* __restrict__ Kg,
    const float* __restrict__ Vg, const void* __restrict__ maskp,
    float* __restrict__ Og)
{
    extern __shared__ float dsm[];   // K stages [0,1], V stages [2,3]

    const int tid  = threadIdx.x;
    const int lane = tid & 31, wid = tid >> 5;
    const int g = lane >> 2, qq = lane & 3;
    const int q0 = blockIdx.x * 128, h = blockIdx.y, b = blockIdx.z;
    const int wide = g_mask_mode;

    const float* Qbase = Qg + ((size_t)(b*SS + q0))*DD + h*HD;
    const float* Kbase = Kg + ((size_t)b*SS)*DD + h*HD;
    const float* Vbase = Vg + ((size_t)b*SS)*DD + h*HD;
    const uint8_t* mask8  = (const uint8_t*)maskp + (size_t)b*SS*SS;
    const int*     mask32 = (const int*)maskp     + (size_t)b*SS*SS;

    const int r0 = wid*16 + g;
    const int r1 = r0 + 8;

    // Q fragments (already tf32-rounded in gemm epilogue); x0.125 is exact
    uint32_t aQ[8][4];
    #pragma unroll
    for (int kt = 0; kt < 8; kt++) {
        const int d0 = kt * 8;
        aQ[kt][0] = __float_as_uint(0.125f * Qbase[(size_t)r0*DD + d0 + qq]);
        aQ[kt][1] = __float_as_uint(0.125f * Qbase[(size_t)r1*DD + d0 + qq]);
        aQ[kt][2] = __float_as_uint(0.125f * Qbase[(size_t)r0*DD + d0 + qq + 4]);
        aQ[kt][3] = __float_as_uint(0.125f * Qbase[(size_t)r1*DD + d0 + qq + 4]);
    }

    // loader mapping
    const int lrow = tid >> 2;        // 0..63
    const int lc0  = (tid & 3) * 16;  // 0,16,32,48
    const float* kp = Kbase + (size_t)lrow*DD + lc0;
    const float* vp = Vbase + (size_t)lrow*DD + lc0;
    const uint32_t k_s = (uint32_t)__cvta_generic_to_shared(dsm + lrow*68 + lc0);
    const uint32_t v_s = k_s + 2*AS_B;

    auto fill = [&](int s, size_t goff) {
        const uint32_t ka = k_s + s*AS_B, va = v_s + s*AS_B;
        const float* kq = kp + goff;
        const float* vq = vp + goff;
        #pragma unroll
        for (int c = 0; c < 4; c++) {
            cp16(ka + c*16, kq + c*4);
            cp16(va + c*16, vq + c*4);
        }
    };

    fill(0, 0); CP_COMMIT();

    float oacc[8][4];
    #pragma unroll
    for (int j = 0; j < 8; j++)
        #pragma unroll
        for (int r = 0; r < 4; r++) oacc[j][r] = 0.f;
    float m0r = -1e30f, m1r = -1e30f, l0 = 0.f, l1 = 0.f;

    const int NT = SS/64;  // 32
    for (int t = 0; t < NT; t++) {
        CP_WAIT(0);
        __syncthreads();
        if (t + 1 < NT) fill((t+1) & 1, (size_t)(t+1)*64*DD);
        CP_COMMIT();

        const float* K0 = dsm + (t & 1)*AS_F;
        const float* V0 = dsm + 2*AS_F + (t & 1)*AS_F;
        const int kv0 = t * 64;

        // mask -> packed bits (2 bits per j: reg0/reg1 columns), rows r0,r1
        unsigned mb0 = 0, mb1 = 0;
        #pragma unroll
        for (int j = 0; j < 8; j++) {
            const int col = kv0 + j*8 + 2*qq;
            unsigned a0, a1, b0, b1;
            if (wide) {
                int2 mA = *(const int2*)(mask32 + (size_t)(q0+r0)*SS + col);
                int2 mB = *(const int2*)(mask32 + (size_t)(q0+r1)*SS + col);
                a0 = mA.x != 0; a1 = mA.y != 0; b0 = mB.x != 0; b1 = mB.y != 0;
            } else {
                unsigned a  = *(const unsigned short*)(mask8 + (size_t)(q0+r0)*SS + col);
                unsigned bm = *(const unsigned short*)(mask8 + (size_t)(q0+r1)*SS + col);
                a0 = a & 0xFFu; a1 = a >> 8; b0 = bm & 0xFFu; b1 = bm >> 8;
            }
            mb0 |= (a0 ? 1u : 0u) << (2*j) | (a1 ? 1u : 0u) << (2*j+1);
            mb1 |= (b0 ? 1u : 0u) << (2*j) | (b1 ? 1u : 0u) << (2*j+1);
        }

        // S = Q K^T
        float sacc[8][4];
        #pragma unroll
        for (int j = 0; j < 8; j++)
            #pragma unroll
            for (int r = 0; r < 4; r++) sacc[j][r] = 0.f;

        #pragma unroll
        for (int kt = 0; kt < 8; kt++) {
            #pragma unroll
            for (int j = 0; j < 8; j++) {
                uint32_t bv[2];
                bv[0] = __float_as_uint(K0[(j*8 + g)*68 + kt*8 + qq]);
                bv[1] = __float_as_uint(K0[(j*8 + g)*68 + kt*8 + qq + 4]);
                mma8(sacc[j], aQ[kt], bv);
            }
        }

        // apply mask
        #pragma unroll
        for (int j = 0; j < 8; j++) {
            if (mb0 & (1u << (2*j)))   sacc[j][0] = -1e30f;
            if (mb0 & (1u << (2*j+1))) sacc[j][1] = -1e30f;
            if (mb1 & (1u << (2*j)))   sacc[j][2] = -1e30f;
            if (mb1 & (1u << (2*j+1))) sacc[j][3] = -1e30f;
        }

        // online softmax (quad reduce)
        float mx0 = -1e30f, mx1 = -1e30f;
        #pragma unroll
        for (int j = 0; j < 8; j++) {
            mx0 = fmaxf(mx0, fmaxf(sacc[j][0], sacc[j][1]));
            mx1 = fmaxf(mx1, fmaxf(sacc[j][2], sacc[j][3]));
        }
        mx0 = fmaxf(mx0, __shfl_xor_sync(0xffffffffu, mx0, 1));
        mx0 = fmaxf(mx0, __shfl_xor_sync(0xffffffffu, mx0, 2));
        mx1 = fmaxf(mx1, __shfl_xor_sync(0xffffffffu, mx1, 1));
        mx1 = fmaxf(mx1, __shfl_xor_sync(0xffffffffu, mx1, 2));

        const float mn0 = fmaxf(m0r, mx0), mn1 = fmaxf(m1r, mx1);
        const float al0 = __expf(m0r - mn0), al1 = __expf(m1r - mn1);
        m0r = mn0; m1r = mn1;

        float s0 = 0.f, s1 = 0.f;
        #pragma unroll
        for (int j = 0; j < 8; j++) {
            float p0 = __expf(sacc[j][0] - mn0);
            float p1 = __expf(sacc[j][1] - mn0);
            float p2 = __expf(sacc[j][2] - mn1);
            float p3 = __expf(sacc[j][3] - mn1);
            sacc[j][0] = p0; sacc[j][1] = p1; sacc[j][2] = p2; sacc[j][3] = p3;
            s0 += p0 + p1; s1 += p2 + p3;
        }
        s0 += __shfl_xor_sync(0xffffffffu, s0, 1);
        s0 += __shfl_xor_sync(0xffffffffu, s0, 2);
        s1 += __shfl_xor_sync(0xffffffffu, s1, 1);
        s1 += __shfl_xor_sync(0xffffffffu, s1, 2);
        l0 = l0*al0 + s0;
        l1 = l1*al1 + s1;
        #pragma unroll
        for (int j = 0; j < 8; j++) {
            oacc[j][0] *= al0; oacc[j][1] *= al0;
            oacc[j][2] *= al1; oacc[j][3] *= al1;
        }

        // O += P @ V : register P, permuted V rows
        #pragma unroll
        for (int kt = 0; kt < 8; kt++) {
            uint32_t aP[4];
            aP[0] = f2tf(sacc[kt][0]);
            aP[1] = f2tf(sacc[kt][2]);
            aP[2] = f2tf(sacc[kt][1]);
            aP[3] = f2tf(sacc[kt][3]);
            #pragma unroll
            for (int j = 0; j < 8; j++) {
                uint32_t bv[2];
                bv[0] = __float_as_uint(V0[(kt*8 + 2*qq    )*68 + j*8 + g]);
                bv[1] = __float_as_uint(V0[(kt*8 + 2*qq + 1)*68 + j*8 + g]);
                mma8(oacc[j], aP, bv);
            }
        }
    }

    // epilogue (write tf32-rounded: feeds the out-proj cp.async path)
    const float inv0 = 1.0f / l0, inv1 = 1.0f / l1;
    #pragma unroll
    for (int j = 0; j < 8; j++) {
        *(float2*)&Og[((size_t)(b*SS + q0 + r0))*DD + h*HD + j*8 + 2*qq] =
            make_float2(u2f(f2tf(oacc[j][0]*inv0)), u2f(f2tf(oacc[j][1]*inv0)));
        *(float2*)&Og[((size_t)(b*SS + q0 + r1))*DD + h*HD + j*8 + 2*qq] =
            make_float2(u2f(f2tf(oacc[j][2]*inv1)), u2f(f2tf(oacc[j][3]*inv1)));
    }
}

// ---------------------------------------------------------------------------
extern "C" void kernel_launch(void* const* d_in, const int* in_sizes, int n_in,
                              void* d_out, int out_size)
{
    const float* query = (const float*)d_in[0];
    const float* key   = (const float*)d_in[1];
    const float* value = (const float*)d_in[2];
    const void*  mask  = d_in[3];
    const float* Wq = (const float*)d_in[4];
    const float* Wk = (const float*)d_in[5];
    const float* Wv = (const float*)d_in[6];
    const float* Wo = (const float*)d_in[7];
    const float* bq = (const float*)d_in[8];
    const float* bk = (const float*)d_in[9];
    const float* bv = (const float*)d_in[10];
    const float* bo = (const float*)d_in[11];
    float* out = (float*)d_out;

    float *Qp, *Kp, *Vp, *AOp, *rqp, *rkp, *rvp, *rWp;
    cudaGetSymbolAddress((void**)&Qp,  g_Q);
    cudaGetSymbolAddress((void**)&Kp,  g_K);
    cudaGetSymbolAddress((void**)&Vp,  g_V);
    cudaGetSymbolAddress((void**)&AOp, g_AO);
    cudaGetSymbolAddress((void**)&rqp, g_rq);
    cudaGetSymbolAddress((void**)&rkp, g_rk);
    cudaGetSymbolAddress((void**)&rvp, g_rv);
    cudaGetSymbolAddress((void**)&rWp, g_rW);

    cudaFuncSetAttribute(gemm_qkv, cudaFuncAttributeMaxDynamicSharedMemorySize, GEMM_SMEM);
    cudaFuncSetAttribute(gemm_out, cudaFuncAttributeMaxDynamicSharedMemorySize, GEMM_SMEM);
    cudaFuncSetAttribute(attn_tf32, cudaFuncAttributeMaxDynamicSharedMemorySize, ATTN_SMEM);

    detect_mask_kernel<<<1, 32>>>((const unsigned int*)mask);

    dim3 rgrid(512, 7);
    round_all<<<rgrid, 256>>>(query, key, value, Wq, Wk, Wv, Wo,
                              rqp, rkp, rvp, rWp);

    dim3 qkv_grid(MM/128, DD/128, 3);   // (32, 8, 3)
    gemm_qkv<<<qkv_grid, 256, GEMM_SMEM>>>(rqp, rkp, rvp, rWp,
                                           bq, bk, bv, Qp, Kp, Vp);

    dim3 agrid(SS/128, HH, BB);         // (16, 16, 2)
    attn_tf32<<<agrid, 256, ATTN_SMEM>>>(Qp, Kp, Vp, mask, AOp);

    dim3 ggrid(MM/128, DD/128);         // (32, 8)
    gemm_out<<<ggrid, 256, GEMM_SMEM>>>(AOp, rWp + (size_t)3*DD*DD, bo, out);
}

// round 7
// speedup vs baseline: 2.1583x; 1.7575x over previous
#include <cuda_runtime.h>
#include <cuda_fp16.h>
#include <cstdint>

#define BB 2
#define SS 2048
#define DD 1024
#define HH 16
#define HD 64
#define MM (BB*SS)   // 4096

// ---- device scratch (halves; no allocations allowed) ----
__device__ __half g_Qh[MM*DD];            // Q proj, scaled by 0.125*log2e
__device__ __half g_Kh[MM*DD];            // K proj
__device__ __half g_Vt[BB*HH*HD*SS];      // V proj, transposed [b][h][d][s]
__device__ __half g_AOh[MM*DD];           // attention output
__device__ __half g_rq[MM*DD];            // rounded inputs
__device__ __half g_rk[MM*DD];
__device__ __half g_rv[MM*DD];
__device__ __half g_rW[4*DD*DD];          // rounded weights
__device__ int    g_mask_mode;            // 0 = u8 bytes, 1 = 4-byte words

#define QSCALE 0.1803368802f  /* 0.125 * log2(e) */

__device__ __forceinline__ uint32_t su32(const void* p) {
    return (uint32_t)__cvta_generic_to_shared(p);
}
__device__ __forceinline__ uint32_t ph2(float lo, float hi) {
    uint32_t r;
    asm("cvt.rn.f16x2.f32 %0, %1, %2;" : "=r"(r) : "f"(hi), "f"(lo));
    return r;
}
__device__ __forceinline__ float ex2(float x) {
    float y; asm("ex2.approx.ftz.f32 %0, %1;" : "=f"(y) : "f"(x)); return y;
}
__device__ __forceinline__ void cp16(uint32_t dst, const void* src) {
    asm volatile("cp.async.cg.shared.global [%0], [%1], 16;" :: "r"(dst), "l"(src));
}
#define CP_COMMIT() asm volatile("cp.async.commit_group;")
#define CP_WAIT(n)  asm volatile("cp.async.wait_group %0;" :: "n"(n))

// D += A(16x16) * B(16x8) ; fp16 inputs, f32 accum
__device__ __forceinline__ void mma16(float* c, const uint32_t* a, const uint32_t* b) {
    asm volatile(
        "mma.sync.aligned.m16n8k16.row.col.f32.f16.f16.f32 "
        "{%0,%1,%2,%3}, {%4,%5,%6,%7}, {%8,%9}, {%0,%1,%2,%3};\n"
        : "+f"(c[0]), "+f"(c[1]), "+f"(c[2]), "+f"(c[3])
        : "r"(a[0]), "r"(a[1]), "r"(a[2]), "r"(a[3]), "r"(b[0]), "r"(b[1]));
}

// ---------------------------------------------------------------------------
__global__ void detect_mask_kernel(const unsigned int* __restrict__ m) {
    if (threadIdx.x == 0 && blockIdx.x == 0) {
        int wide = 1;
        for (int i = 0; i < 256; i++) {
            unsigned v = m[i];
            if (v != 0u && v != 1u && v != 0x3F800000u) { wide = 0; break; }
        }
        g_mask_mode = wide;
    }
}

// ---------------------------------------------------------------------------
// Round inputs + weights f32 -> fp16.
// grid.y: 0..2 inputs (MM*DD), 3..6 weights (DD*DD)
// ---------------------------------------------------------------------------
__global__ __launch_bounds__(256) void round_h(
    const float* __restrict__ q, const float* __restrict__ k, const float* __restrict__ v,
    const float* __restrict__ wq, const float* __restrict__ wk,
    const float* __restrict__ wv, const float* __restrict__ wo,
    __half* __restrict__ rq, __half* __restrict__ rk, __half* __restrict__ rv,
    __half* __restrict__ rW)
{
    const int y = blockIdx.y;
    const float4* src; uint2* dst; int n4;
    if (y < 3) {
        src = (const float4*)(y == 0 ? q : y == 1 ? k : v);
        dst = (uint2*)(y == 0 ? rq : y == 1 ? rk : rv);
        n4 = MM*DD/4;
    } else {
        src = (const float4*)(y == 3 ? wq : y == 4 ? wk : y == 5 ? wv : wo);
        dst = (uint2*)(rW + (size_t)(y-3)*DD*DD);
        n4 = DD*DD/4;
    }
    int i = blockIdx.x*blockDim.x + threadIdx.x;
    const int stride = gridDim.x*blockDim.x;
    for (; i < n4; i += stride) {
        float4 vv = src[i];
        dst[i] = make_uint2(ph2(vv.x, vv.y), ph2(vv.z, vv.w));
    }
}

// ---------------------------------------------------------------------------
// fp16 GEMM: C[m,n] = sum_k A[m,k]*W[n,k] + bias[n], N=K=1024.
// 256 threads (8 warps 2x4), block 128x128, warp 64x32, BK=32 halves,
// 4-stage cp.async. Rows padded to 40 halves (80B) -> conflict-free frags.
// MODE: 0 = f32 out, 1 = half out * QSCALE, 2 = half out, 3 = half out
//       transposed into g_Vt [b][h][d][s].
// ---------------------------------------------------------------------------
#define GSTG 4
#define G_ROWB 80u
#define G_STGB (128u*G_ROWB)       // 10240
#define GEMM_SMEM (2*GSTG*G_STGB)  // 81920
#define G_NIT 32

template<int MODE>
__device__ __forceinline__ void gemm_h_body(
    const __half* __restrict__ A, const __half* __restrict__ W,
    const float* __restrict__ bias, void* __restrict__ Cout)
{
    extern __shared__ char dsmc[];
    char* Ab = dsmc;
    char* Bb = dsmc + GSTG*G_STGB;

    const int tid  = threadIdx.x;
    const int lane = tid & 31, wid = tid >> 5;
    const int g = lane >> 2, qq = lane & 3;
    const int wm = (wid & 1) * 64;
    const int wn = (wid >> 1) * 32;
    const int m0 = blockIdx.x * 128, n0 = blockIdx.y * 128;

    const int lr = tid >> 1;
    const int lh = (tid & 1) * 16;          // half offset in row (0 or 16)

    const __half* Ap = A + (size_t)(m0 + lr) * DD + lh;
    const __half* Wp = W + (size_t)(n0 + lr) * DD + lh;
    const uint32_t a_s = su32(Ab) + (uint32_t)lr*G_ROWB + (uint32_t)lh*2u;
    const uint32_t b_s = su32(Bb) + (uint32_t)lr*G_ROWB + (uint32_t)lh*2u;

    auto fill = [&](int s, int t) {
        const __half* as = Ap + t*32;
        const __half* ws = Wp + t*32;
        const uint32_t aa = a_s + (uint32_t)s*G_STGB;
        const uint32_t ba = b_s + (uint32_t)s*G_STGB;
        cp16(aa,      as);     cp16(aa + 16, as + 8);
        cp16(ba,      ws);     cp16(ba + 16, ws + 8);
    };

    #pragma unroll
    for (int s = 0; s < GSTG-1; s++) { fill(s, s); CP_COMMIT(); }

    float acc[4][4][4];
    #pragma unroll
    for (int i = 0; i < 4; i++)
        #pragma unroll
        for (int j = 0; j < 4; j++)
            #pragma unroll
            for (int r = 0; r < 4; r++) acc[i][j][r] = 0.f;

    for (int it = 0; it < G_NIT; it++) {
        CP_WAIT(GSTG-2);
        __syncthreads();
        if (it + GSTG-1 < G_NIT) fill((it + GSTG-1) & (GSTG-1), it + GSTG-1);
        CP_COMMIT();

        const uint32_t* Aw = (const uint32_t*)(Ab + (size_t)(it & (GSTG-1))*G_STGB);
        const uint32_t* Bw = (const uint32_t*)(Bb + (size_t)(it & (GSTG-1))*G_STGB);

        #pragma unroll
        for (int ks = 0; ks < 2; ks++) {
            const int kw = ks*8 + qq;
            uint32_t aF[4][4], bF[4][2];
            #pragma unroll
            for (int j = 0; j < 4; j++) {
                bF[j][0] = Bw[(wn + j*8 + g)*20 + kw];
                bF[j][1] = Bw[(wn + j*8 + g)*20 + kw + 4];
            }
            #pragma unroll
            for (int i = 0; i < 4; i++) {
                aF[i][0] = Aw[(wm + i*16 + g    )*20 + kw];
                aF[i][1] = Aw[(wm + i*16 + g + 8)*20 + kw];
                aF[i][2] = Aw[(wm + i*16 + g    )*20 + kw + 4];
                aF[i][3] = Aw[(wm + i*16 + g + 8)*20 + kw + 4];
            }
            #pragma unroll
            for (int i = 0; i < 4; i++)
                #pragma unroll
                for (int j = 0; j < 4; j++)
                    mma16(acc[i][j], aF[i], bF[j]);
        }
    }

    #pragma unroll
    for (int j = 0; j < 4; j++) {
        const int col = n0 + wn + j*8 + 2*qq;
        const float2 bv = *(const float2*)&bias[col];
        #pragma unroll
        for (int i = 0; i < 4; i++) {
            const int row = m0 + wm + i*16 + g;
            float2 o0 = make_float2(acc[i][j][0] + bv.x, acc[i][j][1] + bv.y);
            float2 o1 = make_float2(acc[i][j][2] + bv.x, acc[i][j][3] + bv.y);
            if (MODE == 0) {
                float* C = (float*)Cout;
                *(float2*)&C[(size_t)row     * DD + col] = o0;
                *(float2*)&C[(size_t)(row+8) * DD + col] = o1;
            } else if (MODE == 1) {
                __half* C = (__half*)Cout;
                *(uint32_t*)&C[(size_t)row     * DD + col] = ph2(o0.x*QSCALE, o0.y*QSCALE);
                *(uint32_t*)&C[(size_t)(row+8) * DD + col] = ph2(o1.x*QSCALE, o1.y*QSCALE);
            } else if (MODE == 2) {
                __half* C = (__half*)Cout;
                *(uint32_t*)&C[(size_t)row     * DD + col] = ph2(o0.x, o0.y);
                *(uint32_t*)&C[(size_t)(row+8) * DD + col] = ph2(o1.x, o1.y);
            } else {
                __half* VT = (__half*)Cout;
                const int bb = row >> 11;           // row / SS
                const int s  = row & (SS-1);
                const int hh = col >> 6, d = col & 63;
                const size_t base = (((size_t)bb*HH + hh)*HD + d)*SS;
                VT[base        + s]     = __float2half_rn(o0.x);
                VT[base + SS   + s]     = __float2half_rn(o0.y);
                VT[base        + s + 8] = __float2half_rn(o1.x);
                VT[base + SS   + s + 8] = __float2half_rn(o1.y);
            }
        }
    }
}

__global__ __launch_bounds__(256, 2) void gemm_h_qkv(
    const __half* __restrict__ rq, const __half* __restrict__ rk, const __half* __restrict__ rv,
    const __half* __restrict__ rW,
    const float* __restrict__ bq, const float* __restrict__ bk, const float* __restrict__ bv,
    __half* __restrict__ Qh, __half* __restrict__ Kh, __half* __restrict__ Vt)
{
    const int z = blockIdx.z;
    if (z == 0)      gemm_h_body<1>(rq, rW,            bq, Qh);
    else if (z == 1) gemm_h_body<2>(rk, rW + (size_t)DD*DD, bk, Kh);
    else             gemm_h_body<3>(rv, rW + (size_t)2*DD*DD, bv, Vt);
}

__global__ __launch_bounds__(256, 2) void gemm_h_out(
    const __half* __restrict__ A, const __half* __restrict__ W,
    const float* __restrict__ bias, float* __restrict__ C)
{
    gemm_h_body<0>(A, W, bias, C);
}

// ---------------------------------------------------------------------------
// Flash attention, fp16 mma (m16n8k16). Block = (b, h, 128-q tile), 256 thr,
// 8 warps x 16 q rows. KV tiles 64x64, 2-stage cp.async.
// K tile rows [kv][d] (72-half padded), V tile rows [d][kv] (pre-transposed
// in gmem). P stays in registers: S C-frags pack directly into PV A-frags.
// Softmax in exp2 domain (log2e folded into Q).
// ---------------------------------------------------------------------------
#define K_STGB (64u*144u)       // 9216 bytes (64 rows x 72 halves)
#define A_STG  (2u*K_STGB)      // K + V per stage
#define ATTN_SMEM (2*A_STG)     // 36864

__global__ __launch_bounds__(256, 2) void attn_h(
    const __half* __restrict__ Qh, const __half* __restrict__ Kh,
    const __half* __restrict__ Vt, const void* __restrict__ maskp,
    __half* __restrict__ Og)
{
    extern __shared__ char dsmc[];

    const int tid  = threadIdx.x;
    const int lane = tid & 31, wid = tid >> 5;
    const int g = lane >> 2, qq = lane & 3;
    const int q0 = blockIdx.x * 128, h = blockIdx.y, b = blockIdx.z;
    const int wide = g_mask_mode;

    const uint8_t* mask8  = (const uint8_t*)maskp + (size_t)b*SS*SS;
    const int*     mask32 = (const int*)maskp     + (size_t)b*SS*SS;

    const int r0 = wid*16 + g;
    const int r1 = r0 + 8;

    // Q fragments from global (already fp16 * 0.125*log2e)
    const __half* Qb = Qh + ((size_t)(b*SS + q0))*DD + h*HD;
    uint32_t aQ[4][4];
    #pragma unroll
    for (int kt = 0; kt < 4; kt++) {
        aQ[kt][0] = *(const uint32_t*)&Qb[(size_t)r0*DD + kt*16 + 2*qq];
        aQ[kt][1] = *(const uint32_t*)&Qb[(size_t)r1*DD + kt*16 + 2*qq];
        aQ[kt][2] = *(const uint32_t*)&Qb[(size_t)r0*DD + kt*16 + 2*qq + 8];
        aQ[kt][3] = *(const uint32_t*)&Qb[(size_t)r1*DD + kt*16 + 2*qq + 8];
    }

    // loaders: 64 rows, 4 threads/row, 2x16B chunks each
    const int lrow = tid >> 2;
    const int lch  = (tid & 3) * 2;      // chunk pair index (of 8 16B chunks)
    const __half* kp = Kh + ((size_t)b*SS + lrow)*DD + h*HD + lch*8;
    const __half* vp = Vt + (((size_t)b*HH + h)*HD + lrow)*SS + lch*8;
    const uint32_t k_s = su32(dsmc) + (uint32_t)lrow*144u + (uint32_t)lch*16u;
    const uint32_t v_s = k_s + K_STGB;

    auto fill = [&](int s, int t) {
        const uint32_t ka = k_s + (uint32_t)s*A_STG;
        const uint32_t va = v_s + (uint32_t)s*A_STG;
        const __half* kq = kp + (size_t)t*64*DD;
        const __half* vq = vp + t*64;
        cp16(ka,      kq);     cp16(ka + 16, kq + 8);
        cp16(va,      vq);     cp16(va + 16, vq + 8);
    };

    fill(0, 0); CP_COMMIT();

    float oacc[8][4];
    #pragma unroll
    for (int j = 0; j < 8; j++)
        #pragma unroll
        for (int r = 0; r < 4; r++) oacc[j][r] = 0.f;
    float m0r = -1e30f, m1r = -1e30f, l0 = 0.f, l1 = 0.f;

    const int NT = SS/64;
    for (int t = 0; t < NT; t++) {
        CP_WAIT(0);
        __syncthreads();
        if (t + 1 < NT) fill((t+1) & 1, t+1);
        CP_COMMIT();

        const uint32_t* Kw = (const uint32_t*)(dsmc + (size_t)(t & 1)*A_STG);
        const uint32_t* Vw = (const uint32_t*)(dsmc + (size_t)(t & 1)*A_STG + K_STGB);
        const int kv0 = t * 64;

        // mask -> packed bits
        unsigned mb0 = 0, mb1 = 0;
        #pragma unroll
        for (int j = 0; j < 8; j++) {
            const int col = kv0 + j*8 + 2*qq;
            unsigned a0, a1, b0, b1;
            if (wide) {
                int2 mA = *(const int2*)(mask32 + (size_t)(q0+r0)*SS + col);
                int2 mB = *(const int2*)(mask32 + (size_t)(q0+r1)*SS + col);
                a0 = mA.x != 0; a1 = mA.y != 0; b0 = mB.x != 0; b1 = mB.y != 0;
            } else {
                unsigned a  = *(const unsigned short*)(mask8 + (size_t)(q0+r0)*SS + col);
                unsigned bm = *(const unsigned short*)(mask8 + (size_t)(q0+r1)*SS + col);
                a0 = a & 0xFFu; a1 = a >> 8; b0 = bm & 0xFFu; b1 = bm >> 8;
            }
            mb0 |= (a0 ? 1u : 0u) << (2*j) | (a1 ? 1u : 0u) << (2*j+1);
            mb1 |= (b0 ? 1u : 0u) << (2*j) | (b1 ? 1u : 0u) << (2*j+1);
        }

        // S = Q K^T  (4 k-steps of 16 over d)
        float sacc[8][4];
        #pragma unroll
        for (int j = 0; j < 8; j++)
            #pragma unroll
            for (int r = 0; r < 4; r++) sacc[j][r] = 0.f;

        #pragma unroll
        for (int kt = 0; kt < 4; kt++) {
            const int kw = kt*8 + qq;
            #pragma unroll
            for (int j = 0; j < 8; j++) {
                uint32_t bv[2];
                bv[0] = Kw[(j*8 + g)*36 + kw];
                bv[1] = Kw[(j*8 + g)*36 + kw + 4];
                mma16(sacc[j], aQ[kt], bv);
            }
        }

        // apply mask
        #pragma unroll
        for (int j = 0; j < 8; j++) {
            if (mb0 & (1u << (2*j)))   sacc[j][0] = -1e30f;
            if (mb0 & (1u << (2*j+1))) sacc[j][1] = -1e30f;
            if (mb1 & (1u << (2*j)))   sacc[j][2] = -1e30f;
            if (mb1 & (1u << (2*j+1))) sacc[j][3] = -1e30f;
        }

        // online softmax, base-2 domain (quad reduce)
        float mx0 = -1e30f, mx1 = -1e30f;
        #pragma unroll
        for (int j = 0; j < 8; j++) {
            mx0 = fmaxf(mx0, fmaxf(sacc[j][0], sacc[j][1]));
            mx1 = fmaxf(mx1, fmaxf(sacc[j][2], sacc[j][3]));
        }
        mx0 = fmaxf(mx0, __shfl_xor_sync(0xffffffffu, mx0, 1));
        mx0 = fmaxf(mx0, __shfl_xor_sync(0xffffffffu, mx0, 2));
        mx1 = fmaxf(mx1, __shfl_xor_sync(0xffffffffu, mx1, 1));
        mx1 = fmaxf(mx1, __shfl_xor_sync(0xffffffffu, mx1, 2));

        const float mn0 = fmaxf(m0r, mx0), mn1 = fmaxf(m1r, mx1);
        const float al0 = ex2(m0r - mn0), al1 = ex2(m1r - mn1);
        m0r = mn0; m1r = mn1;

        float s0 = 0.f, s1 = 0.f;
        #pragma unroll
        for (int j = 0; j < 8; j++) {
            float p0 = ex2(sacc[j][0] - mn0);
            float p1 = ex2(sacc[j][1] - mn0);
            float p2 = ex2(sacc[j][2] - mn1);
            float p3 = ex2(sacc[j][3] - mn1);
            sacc[j][0] = p0; sacc[j][1] = p1; sacc[j][2] = p2; sacc[j][3] = p3;
            s0 += p0 + p1; s1 += p2 + p3;
        }
        s0 += __shfl_xor_sync(0xffffffffu, s0, 1);
        s0 += __shfl_xor_sync(0xffffffffu, s0, 2);
        s1 += __shfl_xor_sync(0xffffffffu, s1, 1);
        s1 += __shfl_xor_sync(0xffffffffu, s1, 2);
        l0 = l0*al0 + s0;
        l1 = l1*al1 + s1;
        #pragma unroll
        for (int j = 0; j < 8; j++) {
            oacc[j][0] *= al0; oacc[j][1] *= al0;
            oacc[j][2] *= al1; oacc[j][3] *= al1;
        }

        // O += P @ V : C-frags pack straight into A-frags (k=16 over kv)
        #pragma unroll
        for (int kt = 0; kt < 4; kt++) {
            uint32_t aP[4];
            aP[0] = ph2(sacc[2*kt][0],   sacc[2*kt][1]);
            aP[1] = ph2(sacc[2*kt][2],   sacc[2*kt][3]);
            aP[2] = ph2(sacc[2*kt+1][0], sacc[2*kt+1][1]);
            aP[3] = ph2(sacc[2*kt+1][2], sacc[2*kt+1][3]);
            const int kw = kt*8 + qq;
            #pragma unroll
            for (int j = 0; j < 8; j++) {
                uint32_t bv[2];
                bv[0] = Vw[(j*8 + g)*36 + kw];
                bv[1] = Vw[(j*8 + g)*36 + kw + 4];
                mma16(oacc[j], aP, bv);
            }
        }
    }

    // epilogue: normalize, write fp16 (feeds out-proj)
    const float inv0 = 1.0f / l0, inv1 = 1.0f / l1;
    #pragma unroll
    for (int j = 0; j < 8; j++) {
        *(uint32_t*)&Og[((size_t)(b*SS + q0 + r0))*DD + h*HD + j*8 + 2*qq] =
            ph2(oacc[j][0]*inv0, oacc[j][1]*inv0);
        *(uint32_t*)&Og[((size_t)(b*SS + q0 + r1))*DD + h*HD + j*8 + 2*qq] =
            ph2(oacc[j][2]*inv1, oacc[j][3]*inv1);
    }
}

// ---------------------------------------------------------------------------
extern "C" void kernel_launch(void* const* d_in, const int* in_sizes, int n_in,
                              void* d_out, int out_size)
{
    const float* query = (const float*)d_in[0];
    const float* key   = (const float*)d_in[1];
    const float* value = (const float*)d_in[2];
    const void*  mask  = d_in[3];
    const float* Wq = (const float*)d_in[4];
    const float* Wk = (const float*)d_in[5];
    const float* Wv = (const float*)d_in[6];
    const float* Wo = (const float*)d_in[7];
    const float* bq = (const float*)d_in[8];
    const float* bk = (const float*)d_in[9];
    const float* bv = (const float*)d_in[10];
    const float* bo = (const float*)d_in[11];
    float* out = (float*)d_out;

    __half *Qhp, *Khp, *Vtp, *AOp, *rqp, *rkp, *rvp, *rWp;
    cudaGetSymbolAddress((void**)&Qhp, g_Qh);
    cudaGetSymbolAddress((void**)&Khp, g_Kh);
    cudaGetSymbolAddress((void**)&Vtp, g_Vt);
    cudaGetSymbolAddress((void**)&AOp, g_AOh);
    cudaGetSymbolAddress((void**)&rqp, g_rq);
    cudaGetSymbolAddress((void**)&rkp, g_rk);
    cudaGetSymbolAddress((void**)&rvp, g_rv);
    cudaGetSymbolAddress((void**)&rWp, g_rW);

    cudaFuncSetAttribute(gemm_h_qkv, cudaFuncAttributeMaxDynamicSharedMemorySize, GEMM_SMEM);
    cudaFuncSetAttribute(gemm_h_out, cudaFuncAttributeMaxDynamicSharedMemorySize, GEMM_SMEM);
    cudaFuncSetAttribute(attn_h,     cudaFuncAttributeMaxDynamicSharedMemorySize, ATTN_SMEM);

    detect_mask_kernel<<<1, 32>>>((const unsigned int*)mask);

    dim3 rgrid(512, 7);
    round_h<<<rgrid, 256>>>(query, key, value, Wq, Wk, Wv, Wo,
                            rqp, rkp, rvp, rWp);

    dim3 qkv_grid(MM/128, DD/128, 3);   // (32, 8, 3)
    gemm_h_qkv<<<qkv_grid, 256, GEMM_SMEM>>>(rqp, rkp, rvp, rWp,
                                             bq, bk, bv, Qhp, Khp, Vtp);

    dim3 agrid(SS/128, HH, BB);         // (16, 16, 2)
    attn_h<<<agrid, 256, ATTN_SMEM>>>(Qhp, Khp, Vtp, mask, AOp);

    dim3 ggrid(MM/128, DD/128);         // (32, 8)
    gemm_h_out<<<ggrid, 256, GEMM_SMEM>>>(AOp, rWp + (size_t)3*DD*DD, bo, out);
}

// round 8
// speedup vs baseline: 2.6685x; 1.2364x over previous
#include <cuda_runtime.h>
#include <cuda_fp16.h>
#include <cstdint>

#define BB 2
#define SS 2048
#define DD 1024
#define HH 16
#define HD 64
#define MM (BB*SS)   // 4096

// ---- device scratch (no allocations allowed) ----
__device__ __half g_Qh[MM*DD];            // Q proj, scaled by 0.125*log2e
__device__ __half g_Kh[MM*DD];            // K proj
__device__ __half g_Vt[BB*HH*HD*SS];      // V proj, transposed [b][h][d][s]
__device__ __half g_AOh[MM*DD];           // attention output
__device__ __half g_rq[MM*DD];
__device__ __half g_rk[MM*DD];
__device__ __half g_rv[MM*DD];
__device__ __half g_rW[4*DD*DD];
__device__ unsigned long long g_mbits[(size_t)BB*SS*(SS/64)];  // bit-packed mask
__device__ int    g_mask_mode;            // 0 = u8 bytes, 1 = 4-byte words

#define QSCALE 0.1803368802f  /* 0.125 * log2(e) */

__device__ __forceinline__ uint32_t su32(const void* p) {
    return (uint32_t)__cvta_generic_to_shared(p);
}
__device__ __forceinline__ uint32_t ph2(float lo, float hi) {
    uint32_t r;
    asm("cvt.rn.f16x2.f32 %0, %1, %2;" : "=r"(r) : "f"(hi), "f"(lo));
    return r;
}
__device__ __forceinline__ float ex2(float x) {
    float y; asm("ex2.approx.ftz.f32 %0, %1;" : "=f"(y) : "f"(x)); return y;
}
__device__ __forceinline__ void cp16(uint32_t dst, const void* src) {
    asm volatile("cp.async.cg.shared.global [%0], [%1], 16;" :: "r"(dst), "l"(src));
}
#define CP_COMMIT() asm volatile("cp.async.commit_group;")
#define CP_WAIT(n)  asm volatile("cp.async.wait_group %0;" :: "n"(n))

__device__ __forceinline__ void ldsm4(uint32_t* r, uint32_t addr) {
    asm volatile("ldmatrix.sync.aligned.m8n8.x4.shared.b16 {%0,%1,%2,%3}, [%4];"
        : "=r"(r[0]), "=r"(r[1]), "=r"(r[2]), "=r"(r[3]) : "r"(addr));
}

// D += A(16x16) * B(16x8) ; fp16 inputs, f32 accum
__device__ __forceinline__ void mma16(float* c, const uint32_t* a, const uint32_t* b) {
    asm volatile(
        "mma.sync.aligned.m16n8k16.row.col.f32.f16.f16.f32 "
        "{%0,%1,%2,%3}, {%4,%5,%6,%7}, {%8,%9}, {%0,%1,%2,%3};\n"
        : "+f"(c[0]), "+f"(c[1]), "+f"(c[2]), "+f"(c[3])
        : "r"(a[0]), "r"(a[1]), "r"(a[2]), "r"(a[3]), "r"(b[0]), "r"(b[1]));
}

// ---------------------------------------------------------------------------
__global__ void detect_mask_kernel(const unsigned int* __restrict__ m) {
    if (threadIdx.x == 0 && blockIdx.x == 0) {
        int wide = 1;
        for (int i = 0; i < 256; i++) {
            unsigned v = m[i];
            if (v != 0u && v != 1u && v != 0x3F800000u) { wide = 0; break; }
        }
        g_mask_mode = wide;
    }
}

// ---------------------------------------------------------------------------
// Pack mask -> 1 bit per element via warp ballot. Word w covers kv
// [32*(w%64), +32) of logical row w/64 (= b*SS+q).
// ---------------------------------------------------------------------------
__global__ __launch_bounds__(256) void pack_mask(const void* __restrict__ maskp,
                                                 uint32_t* __restrict__ bits)
{
    const int wide = g_mask_mode;
    const int lane = threadIdx.x & 31;
    const int nwords = BB*SS*(SS/32);
    int w = blockIdx.x * (blockDim.x >> 5) + (threadIdx.x >> 5);
    const int stride = gridDim.x * (blockDim.x >> 5);
    for (; w < nwords; w += stride) {
        const size_t row = (size_t)(w >> 6);
        const int kv = (w & 63)*32 + lane;
        unsigned v;
        if (wide) v = ((const uint32_t*)maskp)[row*SS + kv] != 0u;
        else      v = ((const uint8_t*)maskp)[row*SS + kv] != 0u;
        unsigned word = __ballot_sync(0xffffffffu, v);
        if (lane == 0) bits[w] = word;
    }
}

// ---------------------------------------------------------------------------
// Round inputs + weights f32 -> fp16.
// ---------------------------------------------------------------------------
__global__ __launch_bounds__(256) void round_h(
    const float* __restrict__ q, const float* __restrict__ k, const float* __restrict__ v,
    const float* __restrict__ wq, const float* __restrict__ wk,
    const float* __restrict__ wv, const float* __restrict__ wo,
    __half* __restrict__ rq, __half* __restrict__ rk, __half* __restrict__ rv,
    __half* __restrict__ rW)
{
    const int y = blockIdx.y;
    const float4* src; uint2* dst; int n4;
    if (y < 3) {
        src = (const float4*)(y == 0 ? q : y == 1 ? k : v);
        dst = (uint2*)(y == 0 ? rq : y == 1 ? rk : rv);
        n4 = MM*DD/4;
    } else {
        src = (const float4*)(y == 3 ? wq : y == 4 ? wk : y == 5 ? wv : wo);
        dst = (uint2*)(rW + (size_t)(y-3)*DD*DD);
        n4 = DD*DD/4;
    }
    int i = blockIdx.x*blockDim.x + threadIdx.x;
    const int stride = gridDim.x*blockDim.x;
    for (; i < n4; i += stride) {
        float4 vv = src[i];
        dst[i] = make_uint2(ph2(vv.x, vv.y), ph2(vv.z, vv.w));
    }
}

// ---------------------------------------------------------------------------
// fp16 GEMM with ldmatrix fragments. Block 128x128, 256 thr, warp 64x32,
// BK=32 halves, 4-stage cp.async. Rows padded to 40 halves (80B).
// ---------------------------------------------------------------------------
#define GSTG 4
#define G_ROWB 80u
#define G_STGB (128u*G_ROWB)       // 10240
#define GEMM_SMEM (2*GSTG*G_STGB)  // 81920
#define G_NIT 32

template<int MODE>
__device__ __forceinline__ void gemm_h_body(
    const __half* __restrict__ A, const __half* __restrict__ W,
    const float* __restrict__ bias, void* __restrict__ Cout)
{
    extern __shared__ char dsmc[];
    char* Ab = dsmc;
    char* Bb = dsmc + GSTG*G_STGB;

    const int tid  = threadIdx.x;
    const int lane = tid & 31, wid = tid >> 5;
    const int g = lane >> 2, qq = lane & 3;
    const int wm = (wid & 1) * 64;
    const int wn = (wid >> 1) * 32;
    const int m0 = blockIdx.x * 128, n0 = blockIdx.y * 128;

    // ldmatrix lane offsets (bytes), stride 80B
    const uint32_t lmA = ((lane & 7) + ((lane >> 3) & 1)*8)*G_ROWB + (lane >> 4)*16u;
    const uint32_t lmB = ((lane >> 4)*8 + (lane & 7))*G_ROWB + ((lane >> 3) & 1)*16u;

    const int lr = tid >> 1;
    const int lh = (tid & 1) * 16;

    const __half* Ap = A + (size_t)(m0 + lr) * DD + lh;
    const __half* Wp = W + (size_t)(n0 + lr) * DD + lh;
    const uint32_t a_s = su32(Ab) + (uint32_t)lr*G_ROWB + (uint32_t)lh*2u;
    const uint32_t b_s = su32(Bb) + (uint32_t)lr*G_ROWB + (uint32_t)lh*2u;

    auto fill = [&](int s, int t) {
        const __half* as = Ap + t*32;
        const __half* ws = Wp + t*32;
        const uint32_t aa = a_s + (uint32_t)s*G_STGB;
        const uint32_t ba = b_s + (uint32_t)s*G_STGB;
        cp16(aa,      as);     cp16(aa + 16, as + 8);
        cp16(ba,      ws);     cp16(ba + 16, ws + 8);
    };

    #pragma unroll
    for (int s = 0; s < GSTG-1; s++) { fill(s, s); CP_COMMIT(); }

    float acc[4][4][4];
    #pragma unroll
    for (int i = 0; i < 4; i++)
        #pragma unroll
        for (int j = 0; j < 4; j++)
            #pragma unroll
            for (int r = 0; r < 4; r++) acc[i][j][r] = 0.f;

    const uint32_t aW0 = su32(Ab) + (uint32_t)wm*G_ROWB + lmA;
    const uint32_t bW0 = su32(Bb) + (uint32_t)wn*G_ROWB + lmB;

    for (int it = 0; it < G_NIT; it++) {
        CP_WAIT(GSTG-2);
        __syncthreads();
        if (it + GSTG-1 < G_NIT) fill((it + GSTG-1) & (GSTG-1), it + GSTG-1);
        CP_COMMIT();

        const uint32_t stg = (uint32_t)(it & (GSTG-1))*G_STGB;

        #pragma unroll
        for (int ks = 0; ks < 2; ks++) {
            uint32_t aF[4][4], bF[2][4];
            #pragma unroll
            for (int jp = 0; jp < 2; jp++)
                ldsm4(bF[jp], bW0 + stg + (uint32_t)jp*16u*G_ROWB + ks*32u);
            #pragma unroll
            for (int i = 0; i < 4; i++)
                ldsm4(aF[i], aW0 + stg + (uint32_t)i*16u*G_ROWB + ks*32u);
            #pragma unroll
            for (int i = 0; i < 4; i++)
                #pragma unroll
                for (int jp = 0; jp < 2; jp++) {
                    mma16(acc[i][2*jp],   aF[i], &bF[jp][0]);
                    mma16(acc[i][2*jp+1], aF[i], &bF[jp][2]);
                }
        }
    }

    #pragma unroll
    for (int j = 0; j < 4; j++) {
        const int col = n0 + wn + j*8 + 2*qq;
        const float2 bv = *(const float2*)&bias[col];
        #pragma unroll
        for (int i = 0; i < 4; i++) {
            const int row = m0 + wm + i*16 + g;
            float2 o0 = make_float2(acc[i][j][0] + bv.x, acc[i][j][1] + bv.y);
            float2 o1 = make_float2(acc[i][j][2] + bv.x, acc[i][j][3] + bv.y);
            if (MODE == 0) {
                float* C = (float*)Cout;
                *(float2*)&C[(size_t)row     * DD + col] = o0;
                *(float2*)&C[(size_t)(row+8) * DD + col] = o1;
            } else if (MODE == 1) {
                __half* C = (__half*)Cout;
                *(uint32_t*)&C[(size_t)row     * DD + col] = ph2(o0.x*QSCALE, o0.y*QSCALE);
                *(uint32_t*)&C[(size_t)(row+8) * DD + col] = ph2(o1.x*QSCALE, o1.y*QSCALE);
            } else if (MODE == 2) {
                __half* C = (__half*)Cout;
                *(uint32_t*)&C[(size_t)row     * DD + col] = ph2(o0.x, o0.y);
                *(uint32_t*)&C[(size_t)(row+8) * DD + col] = ph2(o1.x, o1.y);
            } else {
                __half* VT = (__half*)Cout;
                const int bb = row >> 11;
                const int s  = row & (SS-1);
                const int hh = col >> 6, d = col & 63;
                const size_t base = (((size_t)bb*HH + hh)*HD + d)*SS;
                VT[base        + s]     = __float2half_rn(o0.x);
                VT[base + SS   + s]     = __float2half_rn(o0.y);
                VT[base        + s + 8] = __float2half_rn(o1.x);
                VT[base + SS   + s + 8] = __float2half_rn(o1.y);
            }
        }
    }
}

__global__ __launch_bounds__(256, 2) void gemm_h_qkv(
    const __half* __restrict__ rq, const __half* __restrict__ rk, const __half* __restrict__ rv,
    const __half* __restrict__ rW,
    const float* __restrict__ bq, const float* __restrict__ bk, const float* __restrict__ bv,
    __half* __restrict__ Qh, __half* __restrict__ Kh, __half* __restrict__ Vt)
{
    const int z = blockIdx.z;
    if (z == 0)      gemm_h_body<1>(rq, rW,                    bq, Qh);
    else if (z == 1) gemm_h_body<2>(rk, rW + (size_t)DD*DD,    bk, Kh);
    else             gemm_h_body<3>(rv, rW + (size_t)2*DD*DD,  bv, Vt);
}

__global__ __launch_bounds__(256, 2) void gemm_h_out(
    const __half* __restrict__ A, const __half* __restrict__ W,
    const float* __restrict__ bias, float* __restrict__ C)
{
    gemm_h_body<0>(A, W, bias, C);
}

// ---------------------------------------------------------------------------
// Flash attention, fp16 mma + ldmatrix + bit-packed mask.
// Block = (b, h, 128-q tile), 256 thr, 8 warps x 16 q rows. KV tiles 64x64,
// 2-stage cp.async. K rows [kv][d], V rows [d][kv] (both 72-half padded).
// ---------------------------------------------------------------------------
#define K_ROWB 144u
#define K_STGB (64u*K_ROWB)     // 9216
#define A_STG  (2u*K_STGB)
#define ATTN_SMEM (2*A_STG)     // 36864

__global__ __launch_bounds__(256, 2) void attn_h(
    const __half* __restrict__ Qh, const __half* __restrict__ Kh,
    const __half* __restrict__ Vt, const uint32_t* __restrict__ mbits,
    __half* __restrict__ Og)
{
    extern __shared__ char dsmc[];

    const int tid  = threadIdx.x;
    const int lane = tid & 31, wid = tid >> 5;
    const int g = lane >> 2, qq = lane & 3;
    const int q0 = blockIdx.x * 128, h = blockIdx.y, b = blockIdx.z;

    const int r0 = wid*16 + g;
    const int r1 = r0 + 8;

    // ldmatrix lane offset for K/V B-frags (stride 144B)
    const uint32_t lmK = ((lane >> 4)*8 + (lane & 7))*K_ROWB + ((lane >> 3) & 1)*16u;

    // Q fragments from global (already fp16 * 0.125*log2e)
    const __half* Qb = Qh + ((size_t)(b*SS + q0))*DD + h*HD;
    uint32_t aQ[4][4];
    #pragma unroll
    for (int kt = 0; kt < 4; kt++) {
        aQ[kt][0] = *(const uint32_t*)&Qb[(size_t)r0*DD + kt*16 + 2*qq];
        aQ[kt][1] = *(const uint32_t*)&Qb[(size_t)r1*DD + kt*16 + 2*qq];
        aQ[kt][2] = *(const uint32_t*)&Qb[(size_t)r0*DD + kt*16 + 2*qq + 8];
        aQ[kt][3] = *(const uint32_t*)&Qb[(size_t)r1*DD + kt*16 + 2*qq + 8];
    }

    // packed mask row pointers (64 u32 words per logical row)
    const uint32_t* mrow0 = mbits + (size_t)(b*SS + q0 + r0)*64;
    const uint32_t* mrow1 = mbits + (size_t)(b*SS + q0 + r1)*64;

    // loaders: 64 rows, 4 threads/row, 2x16B chunks each
    const int lrow = tid >> 2;
    const int lch  = (tid & 3) * 2;
    const __half* kp = Kh + ((size_t)b*SS + lrow)*DD + h*HD + lch*8;
    const __half* vp = Vt + (((size_t)b*HH + h)*HD + lrow)*SS + lch*8;
    const uint32_t k_s = su32(dsmc) + (uint32_t)lrow*K_ROWB + (uint32_t)lch*16u;
    const uint32_t v_s = k_s + K_STGB;

    auto fill = [&](int s, int t) {
        const uint32_t ka = k_s + (uint32_t)s*A_STG;
        const uint32_t va = v_s + (uint32_t)s*A_STG;
        const __half* kq = kp + (size_t)t*64*DD;
        const __half* vq = vp + t*64;
        cp16(ka,      kq);     cp16(ka + 16, kq + 8);
        cp16(va,      vq);     cp16(va + 16, vq + 8);
    };

    fill(0, 0); CP_COMMIT();

    float oacc[8][4];
    #pragma unroll
    for (int j = 0; j < 8; j++)
        #pragma unroll
        for (int r = 0; r < 4; r++) oacc[j][r] = 0.f;
    float m0r = -1e30f, m1r = -1e30f, l0 = 0.f, l1 = 0.f;

    const int NT = SS/64;
    for (int t = 0; t < NT; t++) {
        CP_WAIT(0);
        __syncthreads();
        if (t + 1 < NT) fill((t+1) & 1, t+1);
        CP_COMMIT();

        const uint32_t kS = su32(dsmc) + (uint32_t)(t & 1)*A_STG + lmK;
        const uint32_t vS = kS + K_STGB;

        // mask bits for this tile: 64 bits per row
        uint2 w0v = *(const uint2*)(mrow0 + t*2);
        uint2 w1v = *(const uint2*)(mrow1 + t*2);
        const unsigned long long w0 = (unsigned long long)w0v.x | ((unsigned long long)w0v.y << 32);
        const unsigned long long w1 = (unsigned long long)w1v.x | ((unsigned long long)w1v.y << 32);

        // S = Q K^T
        float sacc[8][4];
        #pragma unroll
        for (int j = 0; j < 8; j++)
            #pragma unroll
            for (int r = 0; r < 4; r++) sacc[j][r] = 0.f;

        #pragma unroll
        for (int kt = 0; kt < 4; kt++) {
            #pragma unroll
            for (int jp = 0; jp < 4; jp++) {
                uint32_t bK[4];
                ldsm4(bK, kS + (uint32_t)jp*16u*K_ROWB + kt*32u);
                mma16(sacc[2*jp],   aQ[kt], &bK[0]);
                mma16(sacc[2*jp+1], aQ[kt], &bK[2]);
            }
        }

        // apply mask (bit p of w = kv column p masked)
        #pragma unroll
        for (int j = 0; j < 8; j++) {
            const int p = j*8 + 2*qq;
            if ((w0 >> p)     & 1ull) sacc[j][0] = -1e30f;
            if ((w0 >> (p+1)) & 1ull) sacc[j][1] = -1e30f;
            if ((w1 >> p)     & 1ull) sacc[j][2] = -1e30f;
            if ((w1 >> (p+1)) & 1ull) sacc[j][3] = -1e30f;
        }

        // online softmax, base-2 domain (quad reduce)
        float mx0 = -1e30f, mx1 = -1e30f;
        #pragma unroll
        for (int j = 0; j < 8; j++) {
            mx0 = fmaxf(mx0, fmaxf(sacc[j][0], sacc[j][1]));
            mx1 = fmaxf(mx1, fmaxf(sacc[j][2], sacc[j][3]));
        }
        mx0 = fmaxf(mx0, __shfl_xor_sync(0xffffffffu, mx0, 1));
        mx0 = fmaxf(mx0, __shfl_xor_sync(0xffffffffu, mx0, 2));
        mx1 = fmaxf(mx1, __shfl_xor_sync(0xffffffffu, mx1, 1));
        mx1 = fmaxf(mx1, __shfl_xor_sync(0xffffffffu, mx1, 2));

        const float mn0 = fmaxf(m0r, mx0), mn1 = fmaxf(m1r, mx1);
        const float al0 = ex2(m0r - mn0), al1 = ex2(m1r - mn1);
        m0r = mn0; m1r = mn1;

        float s0 = 0.f, s1 = 0.f;
        #pragma unroll
        for (int j = 0; j < 8; j++) {
            float p0 = ex2(sacc[j][0] - mn0);
            float p1 = ex2(sacc[j][1] - mn0);
            float p2 = ex2(sacc[j][2] - mn1);
            float p3 = ex2(sacc[j][3] - mn1);
            sacc[j][0] = p0; sacc[j][1] = p1; sacc[j][2] = p2; sacc[j][3] = p3;
            s0 += p0 + p1; s1 += p2 + p3;
        }
        s0 += __shfl_xor_sync(0xffffffffu, s0, 1);
        s0 += __shfl_xor_sync(0xffffffffu, s0, 2);
        s1 += __shfl_xor_sync(0xffffffffu, s1, 1);
        s1 += __shfl_xor_sync(0xffffffffu, s1, 2);
        l0 = l0*al0 + s0;
        l1 = l1*al1 + s1;
        #pragma unroll
        for (int j = 0; j < 8; j++) {
            oacc[j][0] *= al0; oacc[j][1] *= al0;
            oacc[j][2] *= al1; oacc[j][3] *= al1;
        }

        // O += P @ V : C-frags pack straight into A-frags (k over kv)
        #pragma unroll
        for (int kt = 0; kt < 4; kt++) {
            uint32_t aP[4];
            aP[0] = ph2(sacc[2*kt][0],   sacc[2*kt][1]);
            aP[1] = ph2(sacc[2*kt][2],   sacc[2*kt][3]);
            aP[2] = ph2(sacc[2*kt+1][0], sacc[2*kt+1][1]);
            aP[3] = ph2(sacc[2*kt+1][2], sacc[2*kt+1][3]);
            #pragma unroll
            for (int jp = 0; jp < 4; jp++) {
                uint32_t bV[4];
                ldsm4(bV, vS + (uint32_t)jp*16u*K_ROWB + kt*32u);
                mma16(oacc[2*jp],   aP, &bV[0]);
                mma16(oacc[2*jp+1], aP, &bV[2]);
            }
        }
    }

    // epilogue: normalize, write fp16 (feeds out-proj)
    const float inv0 = 1.0f / l0, inv1 = 1.0f / l1;
    #pragma unroll
    for (int j = 0; j < 8; j++) {
        *(uint32_t*)&Og[((size_t)(b*SS + q0 + r0))*DD + h*HD + j*8 + 2*qq] =
            ph2(oacc[j][0]*inv0, oacc[j][1]*inv0);
        *(uint32_t*)&Og[((size_t)(b*SS + q0 + r1))*DD + h*HD + j*8 + 2*qq] =
            ph2(oacc[j][2]*inv1, oacc[j][3]*inv1);
    }
}

// ---------------------------------------------------------------------------
extern "C" void kernel_launch(void* const* d_in, const int* in_sizes, int n_in,
                              void* d_out, int out_size)
{
    const float* query = (const float*)d_in[0];
    const float* key   = (const float*)d_in[1];
    const float* value = (const float*)d_in[2];
    const void*  mask  = d_in[3];
    const float* Wq = (const float*)d_in[4];
    const float* Wk = (const float*)d_in[5];
    const float* Wv = (const float*)d_in[6];
    const float* Wo = (const float*)d_in[7];
    const float* bq = (const float*)d_in[8];
    const float* bk = (const float*)d_in[9];
    const float* bv = (const float*)d_in[10];
    const float* bo = (const float*)d_in[11];
    float* out = (float*)d_out;

    __half *Qhp, *Khp, *Vtp, *AOp, *rqp, *rkp, *rvp, *rWp;
    uint32_t* mbp;
    cudaGetSymbolAddress((void**)&Qhp, g_Qh);
    cudaGetSymbolAddress((void**)&Khp, g_Kh);
    cudaGetSymbolAddress((void**)&Vtp, g_Vt);
    cudaGetSymbolAddress((void**)&AOp, g_AOh);
    cudaGetSymbolAddress((void**)&rqp, g_rq);
    cudaGetSymbolAddress((void**)&rkp, g_rk);
    cudaGetSymbolAddress((void**)&rvp, g_rv);
    cudaGetSymbolAddress((void**)&rWp, g_rW);
    cudaGetSymbolAddress((void**)&mbp, g_mbits);

    cudaFuncSetAttribute(gemm_h_qkv, cudaFuncAttributeMaxDynamicSharedMemorySize, GEMM_SMEM);
    cudaFuncSetAttribute(gemm_h_out, cudaFuncAttributeMaxDynamicSharedMemorySize, GEMM_SMEM);
    cudaFuncSetAttribute(attn_h,     cudaFuncAttributeMaxDynamicSharedMemorySize, ATTN_SMEM);

    detect_mask_kernel<<<1, 32>>>((const unsigned int*)mask);

    pack_mask<<<1024, 256>>>(mask, mbp);

    dim3 rgrid(512, 7);
    round_h<<<rgrid, 256>>>(query, key, value, Wq, Wk, Wv, Wo,
                            rqp, rkp, rvp, rWp);

    dim3 qkv_grid(MM/128, DD/128, 3);   // (32, 8, 3)
    gemm_h_qkv<<<qkv_grid, 256, GEMM_SMEM>>>(rqp, rkp, rvp, rWp,
                                             bq, bk, bv, Qhp, Khp, Vtp);

    dim3 agrid(SS/128, HH, BB);         // (16, 16, 2)
    attn_h<<<agrid, 256, ATTN_SMEM>>>(Qhp, Khp, Vtp, mbp, AOp);

    dim3 ggrid(MM/128, DD/128);         // (32, 8)
    gemm_h_out<<<ggrid, 256, GEMM_SMEM>>>(AOp, rWp + (size_t)3*DD*DD, bo, out);
}

// round 9
// speedup vs baseline: 2.7663x; 1.0366x over previous
#include <cuda_runtime.h>
#include <cuda_fp16.h>
#include <cstdint>

#define BB 2
#define SS 2048
#define DD 1024
#define HH 16
#define HD 64
#define MM (BB*SS)   // 4096

// ---- device scratch (no allocations allowed) ----
__device__ __half g_Qh[MM*DD];            // Q proj, scaled by 0.125*log2e
__device__ __half g_Kh[MM*DD];            // K proj
__device__ __half g_Vt[BB*HH*HD*SS];      // V proj, transposed [b][h][d][s]
__device__ __half g_AOh[MM*DD];           // attention output
__device__ __half g_rq[MM*DD];
__device__ __half g_rk[MM*DD];
__device__ __half g_rv[MM*DD];
__device__ __half g_rW[4*DD*DD];
__device__ uint32_t g_mbits[(size_t)BB*SS*(SS/32)];  // bit-packed mask (1MB)

#define QSCALE 0.1803368802f  /* 0.125 * log2(e) */

__device__ __forceinline__ uint32_t su32(const void* p) {
    return (uint32_t)__cvta_generic_to_shared(p);
}
__device__ __forceinline__ uint32_t ph2(float lo, float hi) {
    uint32_t r;
    asm("cvt.rn.f16x2.f32 %0, %1, %2;" : "=r"(r) : "f"(hi), "f"(lo));
    return r;
}
__device__ __forceinline__ float ex2(float x) {
    float y; asm("ex2.approx.ftz.f32 %0, %1;" : "=f"(y) : "f"(x)); return y;
}
__device__ __forceinline__ uint32_t hex2(uint32_t x) {
    uint32_t y; asm("ex2.approx.f16x2 %0, %1;" : "=r"(y) : "r"(x)); return y;
}
__device__ __forceinline__ void cp16(uint32_t dst, const void* src) {
    asm volatile("cp.async.cg.shared.global [%0], [%1], 16;" :: "r"(dst), "l"(src));
}
#define CP_COMMIT() asm volatile("cp.async.commit_group;")
#define CP_WAIT(n)  asm volatile("cp.async.wait_group %0;" :: "n"(n))

__device__ __forceinline__ void ldsm4(uint32_t* r, uint32_t addr) {
    asm volatile("ldmatrix.sync.aligned.m8n8.x4.shared.b16 {%0,%1,%2,%3}, [%4];"
        : "=r"(r[0]), "=r"(r[1]), "=r"(r[2]), "=r"(r[3]) : "r"(addr));
}

// D += A(16x16) * B(16x8) ; fp16 inputs, f32 accum
__device__ __forceinline__ void mma16(float* c, const uint32_t* a, const uint32_t* b) {
    asm volatile(
        "mma.sync.aligned.m16n8k16.row.col.f32.f16.f16.f32 "
        "{%0,%1,%2,%3}, {%4,%5,%6,%7}, {%8,%9}, {%0,%1,%2,%3};\n"
        : "+f"(c[0]), "+f"(c[1]), "+f"(c[2]), "+f"(c[3])
        : "r"(a[0]), "r"(a[1]), "r"(a[2]), "r"(a[3]), "r"(b[0]), "r"(b[1]));
}

// ---------------------------------------------------------------------------
// Fused prep: y<3 round inputs, y in 3..6 round weights, y==7 pack mask bits
// (with inline warp-parallel mask-dtype sniff; bool-as-bytes vs 4-byte words).
// ---------------------------------------------------------------------------
__global__ __launch_bounds__(256) void prep(
    const float* __restrict__ q, const float* __restrict__ k, const float* __restrict__ v,
    const float* __restrict__ wq, const float* __restrict__ wk,
    const float* __restrict__ wv, const float* __restrict__ wo,
    const void* __restrict__ maskp,
    __half* __restrict__ rq, __half* __restrict__ rk, __half* __restrict__ rv,
    __half* __restrict__ rW, uint32_t* __restrict__ bits)
{
    const int y = blockIdx.y;
    if (y < 7) {
        const float4* src; uint2* dst; int n4;
        if (y < 3) {
            src = (const float4*)(y == 0 ? q : y == 1 ? k : v);
            dst = (uint2*)(y == 0 ? rq : y == 1 ? rk : rv);
            n4 = MM*DD/4;
        } else {
            src = (const float4*)(y == 3 ? wq : y == 4 ? wk : y == 5 ? wv : wo);
            dst = (uint2*)(rW + (size_t)(y-3)*DD*DD);
            n4 = DD*DD/4;
        }
        int i = blockIdx.x*blockDim.x + threadIdx.x;
        const int stride = gridDim.x*blockDim.x;
        for (; i < n4; i += stride) {
            float4 vv = src[i];
            dst[i] = make_uint2(ph2(vv.x, vv.y), ph2(vv.z, vv.w));
        }
    } else {
        const int lane = threadIdx.x & 31;
        const uint32_t* m32 = (const uint32_t*)maskp;
        // inline dtype sniff: first 256 u32 words, warp-parallel
        unsigned bad = 0;
        #pragma unroll
        for (int i = 0; i < 8; i++) {
            unsigned vv = m32[lane*8 + i];
            bad |= (vv > 1u && vv != 0x3F800000u) ? 1u : 0u;
        }
        const int wide = (__ballot_sync(0xffffffffu, bad) == 0u);

        const int nwords = BB*SS*(SS/32);
        int w = blockIdx.x*(blockDim.x >> 5) + (threadIdx.x >> 5);
        const int stride = gridDim.x*(blockDim.x >> 5);
        for (; w < nwords; w += stride) {
            const size_t row = (size_t)(w >> 6);
            const int kv = (w & 63)*32 + lane;
            unsigned vb;
            if (wide) vb = m32[row*SS + kv] != 0u;
            else      vb = ((const uint8_t*)maskp)[row*SS + kv] != 0u;
            unsigned word = __ballot_sync(0xffffffffu, vb);
            if (lane == 0) bits[w] = word;
        }
    }
}

// ---------------------------------------------------------------------------
// fp16 GEMM with ldmatrix fragments (unchanged from R8). Block 128x128,
// 256 thr, warp 64x32, BK=32 halves, 4-stage cp.async, rows padded to 80B.
// ---------------------------------------------------------------------------
#define GSTG 4
#define G_ROWB 80u
#define G_STGB (128u*G_ROWB)       // 10240
#define GEMM_SMEM (2*GSTG*G_STGB)  // 81920
#define G_NIT 32

template<int MODE>
__device__ __forceinline__ void gemm_h_body(
    const __half* __restrict__ A, const __half* __restrict__ W,
    const float* __restrict__ bias, void* __restrict__ Cout)
{
    extern __shared__ char dsmc[];
    char* Ab = dsmc;
    char* Bb = dsmc + GSTG*G_STGB;

    const int tid  = threadIdx.x;
    const int lane = tid & 31, wid = tid >> 5;
    const int g = lane >> 2, qq = lane & 3;
    const int wm = (wid & 1) * 64;
    const int wn = (wid >> 1) * 32;
    const int m0 = blockIdx.x * 128, n0 = blockIdx.y * 128;

    const uint32_t lmA = ((lane & 7) + ((lane >> 3) & 1)*8)*G_ROWB + (lane >> 4)*16u;
    const uint32_t lmB = ((lane >> 4)*8 + (lane & 7))*G_ROWB + ((lane >> 3) & 1)*16u;

    const int lr = tid >> 1;
    const int lh = (tid & 1) * 16;

    const __half* Ap = A + (size_t)(m0 + lr) * DD + lh;
    const __half* Wp = W + (size_t)(n0 + lr) * DD + lh;
    const uint32_t a_s = su32(Ab) + (uint32_t)lr*G_ROWB + (uint32_t)lh*2u;
    const uint32_t b_s = su32(Bb) + (uint32_t)lr*G_ROWB + (uint32_t)lh*2u;

    auto fill = [&](int s, int t) {
        const __half* as = Ap + t*32;
        const __half* ws = Wp + t*32;
        const uint32_t aa = a_s + (uint32_t)s*G_STGB;
        const uint32_t ba = b_s + (uint32_t)s*G_STGB;
        cp16(aa,      as);     cp16(aa + 16, as + 8);
        cp16(ba,      ws);     cp16(ba + 16, ws + 8);
    };

    #pragma unroll
    for (int s = 0; s < GSTG-1; s++) { fill(s, s); CP_COMMIT(); }

    float acc[4][4][4];
    #pragma unroll
    for (int i = 0; i < 4; i++)
        #pragma unroll
        for (int j = 0; j < 4; j++)
            #pragma unroll
            for (int r = 0; r < 4; r++) acc[i][j][r] = 0.f;

    const uint32_t aW0 = su32(Ab) + (uint32_t)wm*G_ROWB + lmA;
    const uint32_t bW0 = su32(Bb) + (uint32_t)wn*G_ROWB + lmB;

    for (int it = 0; it < G_NIT; it++) {
        CP_WAIT(GSTG-2);
        __syncthreads();
        if (it + GSTG-1 < G_NIT) fill((it + GSTG-1) & (GSTG-1), it + GSTG-1);
        CP_COMMIT();

        const uint32_t stg = (uint32_t)(it & (GSTG-1))*G_STGB;

        #pragma unroll
        for (int ks = 0; ks < 2; ks++) {
            uint32_t aF[4][4], bF[2][4];
            #pragma unroll
            for (int jp = 0; jp < 2; jp++)
                ldsm4(bF[jp], bW0 + stg + (uint32_t)jp*16u*G_ROWB + ks*32u);
            #pragma unroll
            for (int i = 0; i < 4; i++)
                ldsm4(aF[i], aW0 + stg + (uint32_t)i*16u*G_ROWB + ks*32u);
            #pragma unroll
            for (int i = 0; i < 4; i++)
                #pragma unroll
                for (int jp = 0; jp < 2; jp++) {
                    mma16(acc[i][2*jp],   aF[i], &bF[jp][0]);
                    mma16(acc[i][2*jp+1], aF[i], &bF[jp][2]);
                }
        }
    }

    #pragma unroll
    for (int j = 0; j < 4; j++) {
        const int col = n0 + wn + j*8 + 2*qq;
        const float2 bv = *(const float2*)&bias[col];
        #pragma unroll
        for (int i = 0; i < 4; i++) {
            const int row = m0 + wm + i*16 + g;
            float2 o0 = make_float2(acc[i][j][0] + bv.x, acc[i][j][1] + bv.y);
            float2 o1 = make_float2(acc[i][j][2] + bv.x, acc[i][j][3] + bv.y);
            if (MODE == 0) {
                float* C = (float*)Cout;
                *(float2*)&C[(size_t)row     * DD + col] = o0;
                *(float2*)&C[(size_t)(row+8) * DD + col] = o1;
            } else if (MODE == 1) {
                __half* C = (__half*)Cout;
                *(uint32_t*)&C[(size_t)row     * DD + col] = ph2(o0.x*QSCALE, o0.y*QSCALE);
                *(uint32_t*)&C[(size_t)(row+8) * DD + col] = ph2(o1.x*QSCALE, o1.y*QSCALE);
            } else if (MODE == 2) {
                __half* C = (__half*)Cout;
                *(uint32_t*)&C[(size_t)row     * DD + col] = ph2(o0.x, o0.y);
                *(uint32_t*)&C[(size_t)(row+8) * DD + col] = ph2(o1.x, o1.y);
            } else {
                __half* VT = (__half*)Cout;
                const int bb = row >> 11;
                const int s  = row & (SS-1);
                const int hh = col >> 6, d = col & 63;
                const size_t base = (((size_t)bb*HH + hh)*HD + d)*SS;
                VT[base        + s]     = __float2half_rn(o0.x);
                VT[base + SS   + s]     = __float2half_rn(o0.y);
                VT[base        + s + 8] = __float2half_rn(o1.x);
                VT[base + SS   + s + 8] = __float2half_rn(o1.y);
            }
        }
    }
}

__global__ __launch_bounds__(256, 2) void gemm_h_qkv(
    const __half* __restrict__ rq, const __half* __restrict__ rk, const __half* __restrict__ rv,
    const __half* __restrict__ rW,
    const float* __restrict__ bq, const float* __restrict__ bk, const float* __restrict__ bv,
    __half* __restrict__ Qh, __half* __restrict__ Kh, __half* __restrict__ Vt)
{
    const int z = blockIdx.z;
    if (z == 0)      gemm_h_body<1>(rq, rW,                    bq, Qh);
    else if (z == 1) gemm_h_body<2>(rk, rW + (size_t)DD*DD,    bk, Kh);
    else             gemm_h_body<3>(rv, rW + (size_t)2*DD*DD,  bv, Vt);
}

__global__ __launch_bounds__(256, 2) void gemm_h_out(
    const __half* __restrict__ A, const __half* __restrict__ W,
    const float* __restrict__ bias, float* __restrict__ C)
{
    gemm_h_body<0>(A, W, bias, C);
}

// ---------------------------------------------------------------------------
// Flash attention: fp16 mma + ldmatrix + bit mask + f16x2 exp2 + l-via-MMA.
// Block = (b, h, 128-q tile), 256 thr, 8 warps x 16 q rows. KV tiles 64x64,
// 2-stage cp.async. K rows [kv][d], V rows [d][kv] (72-half padded).
// ---------------------------------------------------------------------------
#define K_ROWB 144u
#define K_STGB (64u*K_ROWB)     // 9216
#define A_STG  (2u*K_STGB)
#define ATTN_SMEM (2*A_STG)     // 36864

__global__ __launch_bounds__(256, 2) void attn_h(
    const __half* __restrict__ Qh, const __half* __restrict__ Kh,
    const __half* __restrict__ Vt, const uint32_t* __restrict__ mbits,
    __half* __restrict__ Og)
{
    extern __shared__ char dsmc[];

    const int tid  = threadIdx.x;
    const int lane = tid & 31, wid = tid >> 5;
    const int g = lane >> 2, qq = lane & 3;
    const int q0 = blockIdx.x * 128, h = blockIdx.y, b = blockIdx.z;

    const int r0 = wid*16 + g;
    const int r1 = r0 + 8;

    const uint32_t lmK = ((lane >> 4)*8 + (lane & 7))*K_ROWB + ((lane >> 3) & 1)*16u;

    const __half* Qb = Qh + ((size_t)(b*SS + q0))*DD + h*HD;
    uint32_t aQ[4][4];
    #pragma unroll
    for (int kt = 0; kt < 4; kt++) {
        aQ[kt][0] = *(const uint32_t*)&Qb[(size_t)r0*DD + kt*16 + 2*qq];
        aQ[kt][1] = *(const uint32_t*)&Qb[(size_t)r1*DD + kt*16 + 2*qq];
        aQ[kt][2] = *(const uint32_t*)&Qb[(size_t)r0*DD + kt*16 + 2*qq + 8];
        aQ[kt][3] = *(const uint32_t*)&Qb[(size_t)r1*DD + kt*16 + 2*qq + 8];
    }

    const uint32_t* mrow0 = mbits + (size_t)(b*SS + q0 + r0)*64;
    const uint32_t* mrow1 = mbits + (size_t)(b*SS + q0 + r1)*64;

    const int lrow = tid >> 2;
    const int lch  = (tid & 3) * 2;
    const __half* kp = Kh + ((size_t)b*SS + lrow)*DD + h*HD + lch*8;
    const __half* vp = Vt + (((size_t)b*HH + h)*HD + lrow)*SS + lch*8;
    const uint32_t k_s = su32(dsmc) + (uint32_t)lrow*K_ROWB + (uint32_t)lch*16u;
    const uint32_t v_s = k_s + K_STGB;

    auto fill = [&](int s, int t) {
        const uint32_t ka = k_s + (uint32_t)s*A_STG;
        const uint32_t va = v_s + (uint32_t)s*A_STG;
        const __half* kq = kp + (size_t)t*64*DD;
        const __half* vq = vp + t*64;
        cp16(ka,      kq);     cp16(ka + 16, kq + 8);
        cp16(va,      vq);     cp16(va + 16, vq + 8);
    };

    fill(0, 0); CP_COMMIT();

    float oacc[8][4];
    #pragma unroll
    for (int j = 0; j < 8; j++)
        #pragma unroll
        for (int r = 0; r < 4; r++) oacc[j][r] = 0.f;
    float lacc[4] = {0.f, 0.f, 0.f, 0.f};     // row-sum accum via ones-MMA
    float m0r = -1e30f, m1r = -1e30f;

    const uint32_t ones2[2] = {0x3C003C00u, 0x3C003C00u};

    const int NT = SS/64;
    for (int t = 0; t < NT; t++) {
        CP_WAIT(0);
        __syncthreads();
        if (t + 1 < NT) fill((t+1) & 1, t+1);
        CP_COMMIT();

        const uint32_t kS = su32(dsmc) + (uint32_t)(t & 1)*A_STG + lmK;
        const uint32_t vS = kS + K_STGB;

        uint2 w0v = *(const uint2*)(mrow0 + t*2);
        uint2 w1v = *(const uint2*)(mrow1 + t*2);
        const unsigned long long w0 = (unsigned long long)w0v.x | ((unsigned long long)w0v.y << 32);
        const unsigned long long w1 = (unsigned long long)w1v.x | ((unsigned long long)w1v.y << 32);

        // S = Q K^T
        float sacc[8][4];
        #pragma unroll
        for (int j = 0; j < 8; j++)
            #pragma unroll
            for (int r = 0; r < 4; r++) sacc[j][r] = 0.f;

        #pragma unroll
        for (int kt = 0; kt < 4; kt++) {
            #pragma unroll
            for (int jp = 0; jp < 4; jp++) {
                uint32_t bK[4];
                ldsm4(bK, kS + (uint32_t)jp*16u*K_ROWB + kt*32u);
                mma16(sacc[2*jp],   aQ[kt], &bK[0]);
                mma16(sacc[2*jp+1], aQ[kt], &bK[2]);
            }
        }

        // apply mask
        #pragma unroll
        for (int j = 0; j < 8; j++) {
            const int p = j*8 + 2*qq;
            if ((w0 >> p)     & 1ull) sacc[j][0] = -1e30f;
            if ((w0 >> (p+1)) & 1ull) sacc[j][1] = -1e30f;
            if ((w1 >> p)     & 1ull) sacc[j][2] = -1e30f;
            if ((w1 >> (p+1)) & 1ull) sacc[j][3] = -1e30f;
        }

        // running max (quad reduce)
        float mx0 = -1e30f, mx1 = -1e30f;
        #pragma unroll
        for (int j = 0; j < 8; j++) {
            mx0 = fmaxf(mx0, fmaxf(sacc[j][0], sacc[j][1]));
            mx1 = fmaxf(mx1, fmaxf(sacc[j][2], sacc[j][3]));
        }
        mx0 = fmaxf(mx0, __shfl_xor_sync(0xffffffffu, mx0, 1));
        mx0 = fmaxf(mx0, __shfl_xor_sync(0xffffffffu, mx0, 2));
        mx1 = fmaxf(mx1, __shfl_xor_sync(0xffffffffu, mx1, 1));
        mx1 = fmaxf(mx1, __shfl_xor_sync(0xffffffffu, mx1, 2));

        const float mn0 = fmaxf(m0r, mx0), mn1 = fmaxf(m1r, mx1);
        const float al0 = ex2(m0r - mn0), al1 = ex2(m1r - mn1);
        m0r = mn0; m1r = mn1;

        // rescale accumulators
        lacc[0] *= al0; lacc[1] *= al0; lacc[2] *= al1; lacc[3] *= al1;
        #pragma unroll
        for (int j = 0; j < 8; j++) {
            oacc[j][0] *= al0; oacc[j][1] *= al0;
            oacc[j][2] *= al1; oacc[j][3] *= al1;
        }

        // P = exp2(S - mn) in f16x2; feed PV MMA and the l ones-MMA
        #pragma unroll
        for (int kt = 0; kt < 4; kt++) {
            uint32_t aP[4];
            aP[0] = hex2(ph2(sacc[2*kt][0]   - mn0, sacc[2*kt][1]   - mn0));
            aP[1] = hex2(ph2(sacc[2*kt][2]   - mn1, sacc[2*kt][3]   - mn1));
            aP[2] = hex2(ph2(sacc[2*kt+1][0] - mn0, sacc[2*kt+1][1] - mn0));
            aP[3] = hex2(ph2(sacc[2*kt+1][2] - mn1, sacc[2*kt+1][3] - mn1));
            mma16(lacc, aP, ones2);
            #pragma unroll
            for (int jp = 0; jp < 4; jp++) {
                uint32_t bV[4];
                ldsm4(bV, vS + (uint32_t)jp*16u*K_ROWB + kt*32u);
                mma16(oacc[2*jp],   aP, &bV[0]);
                mma16(oacc[2*jp+1], aP, &bV[2]);
            }
        }
    }

    // epilogue: l lives in lacc (all cols equal; [0]=row r0, [2]=row r1)
    const float inv0 = 1.0f / lacc[0], inv1 = 1.0f / lacc[2];
    #pragma unroll
    for (int j = 0; j < 8; j++) {
        *(uint32_t*)&Og[((size_t)(b*SS + q0 + r0))*DD + h*HD + j*8 + 2*qq] =
            ph2(oacc[j][0]*inv0, oacc[j][1]*inv0);
        *(uint32_t*)&Og[((size_t)(b*SS + q0 + r1))*DD + h*HD + j*8 + 2*qq] =
            ph2(oacc[j][2]*inv1, oacc[j][3]*inv1);
    }
}

// ---------------------------------------------------------------------------
extern "C" void kernel_launch(void* const* d_in, const int* in_sizes, int n_in,
                              void* d_out, int out_size)
{
    const float* query = (const float*)d_in[0];
    const float* key   = (const float*)d_in[1];
    const float* value = (const float*)d_in[2];
    const void*  mask  = d_in[3];
    const float* Wq = (const float*)d_in[4];
    const float* Wk = (const float*)d_in[5];
    const float* Wv = (const float*)d_in[6];
    const float* Wo = (const float*)d_in[7];
    const float* bq = (const float*)d_in[8];
    const float* bk = (const float*)d_in[9];
    const float* bv = (const float*)d_in[10];
    const float* bo = (const float*)d_in[11];
    float* out = (float*)d_out;

    __half *Qhp, *Khp, *Vtp, *AOp, *rqp, *rkp, *rvp, *rWp;
    uint32_t* mbp;
    cudaGetSymbolAddress((void**)&Qhp, g_Qh);
    cudaGetSymbolAddress((void**)&Khp, g_Kh);
    cudaGetSymbolAddress((void**)&Vtp, g_Vt);
    cudaGetSymbolAddress((void**)&AOp, g_AOh);
    cudaGetSymbolAddress((void**)&rqp, g_rq);
    cudaGetSymbolAddress((void**)&rkp, g_rk);
    cudaGetSymbolAddress((void**)&rvp, g_rv);
    cudaGetSymbolAddress((void**)&rWp, g_rW);
    cudaGetSymbolAddress((void**)&mbp, g_mbits);

    cudaFuncSetAttribute(gemm_h_qkv, cudaFuncAttributeMaxDynamicSharedMemorySize, GEMM_SMEM);
    cudaFuncSetAttribute(gemm_h_out, cudaFuncAttributeMaxDynamicSharedMemorySize, GEMM_SMEM);
    cudaFuncSetAttribute(attn_h,     cudaFuncAttributeMaxDynamicSharedMemorySize, ATTN_SMEM);

    dim3 pgrid(512, 8);
    prep<<<pgrid, 256>>>(query, key, value, Wq, Wk, Wv, Wo, mask,
                         rqp, rkp, rvp, rWp, mbp);

    dim3 qkv_grid(MM/128, DD/128, 3);   // (32, 8, 3)
    gemm_h_qkv<<<qkv_grid, 256, GEMM_SMEM>>>(rqp, rkp, rvp, rWp,
                                             bq, bk, bv, Qhp, Khp, Vtp);

    dim3 agrid(SS/128, HH, BB);         // (16, 16, 2)
    attn_h<<<agrid, 256, ATTN_SMEM>>>(Qhp, Khp, Vtp, mbp, AOp);

    dim3 ggrid(MM/128, DD/128);         // (32, 8)
    gemm_h_out<<<ggrid, 256, GEMM_SMEM>>>(AOp, rWp + (size_t)3*DD*DD, bo, out);
}